// round 2
// baseline (speedup 1.0000x reference)
#include <cuda_runtime.h>
#include <math.h>

#define SEQ 2048
#define DM 1024
#define NH 16
#define DK 64

// Scratch (static device globals — no runtime allocation allowed)
__device__ float g_Q[SEQ * DM];
__device__ float g_K[SEQ * DM];
__device__ float g_V[SEQ * DM];
__device__ float g_BR[SEQ * DM];

// ---------------------------------------------------------------------------
// Kernel 1: batched projection GEMM.  C[n][h*64+k] = sum_d X[n][d] * W[d][...]
// z = 0:Q, 1:K, 2:V, 3:b_rotate.
// 128x128 tile, 256 threads, 8x8 micro-tile, BK=16, double-buffered smem.
// ---------------------------------------------------------------------------
__global__ __launch_bounds__(256) void proj_gemm(
    const float* __restrict__ query, const float* __restrict__ key,
    const float* __restrict__ value, const float* __restrict__ bemb,
    const float* __restrict__ LL, const float* __restrict__ bproj)
{
    int z = blockIdx.z;
    const float* X = (z == 0) ? query : (z == 1) ? key : (z == 2) ? value : bemb;
    const float* W = (z < 3) ? (LL + (size_t)z * DM * DM) : bproj;
    float* C = (z == 0) ? g_Q : (z == 1) ? g_K : (z == 2) ? g_V : g_BR;

    __shared__ float As[2][16][128];   // [buf][k][m]  (A transposed)
    __shared__ float Bs[2][16][128];   // [buf][k][n]

    int tid = threadIdx.x;
    int tx = tid & 15, ty = tid >> 4;
    int m0 = blockIdx.y * 128, n0 = blockIdx.x * 128;

    // A tile: 128 rows x 16 cols = 512 float4; thread handles f=tid, tid+256
    int ar0 = tid >> 2,        ac0 = (tid & 3) * 4;
    int ar1 = (tid + 256) >> 2, ac1 = ((tid + 256) & 3) * 4;
    // B tile: 16 rows x 128 cols = 512 float4
    int brw0 = tid >> 5,        bc0 = (tid & 31) * 4;
    int brw1 = (tid + 256) >> 5, bc1 = ((tid + 256) & 31) * 4;

    const float* A0 = X + (size_t)(m0 + ar0) * DM + ac0;
    const float* A1 = X + (size_t)(m0 + ar1) * DM + ac1;
    const float* B0 = W + (size_t)brw0 * DM + n0 + bc0;
    const float* B1 = W + (size_t)brw1 * DM + n0 + bc1;

    float4 a0 = *(const float4*)(A0);
    float4 a1 = *(const float4*)(A1);
    float4 b0 = *(const float4*)(B0);
    float4 b1 = *(const float4*)(B1);

    // store tile 0 into buffer 0
    As[0][ac0 + 0][ar0] = a0.x; As[0][ac0 + 1][ar0] = a0.y;
    As[0][ac0 + 2][ar0] = a0.z; As[0][ac0 + 3][ar0] = a0.w;
    As[0][ac1 + 0][ar1] = a1.x; As[0][ac1 + 1][ar1] = a1.y;
    As[0][ac1 + 2][ar1] = a1.z; As[0][ac1 + 3][ar1] = a1.w;
    *(float4*)&Bs[0][brw0][bc0] = b0;
    *(float4*)&Bs[0][brw1][bc1] = b1;
    __syncthreads();

    float acc[8][8] = {};
    int buf = 0;

    for (int k0 = 0; k0 < DM; k0 += 16) {
        bool more = (k0 + 16) < DM;
        if (more) {
            a0 = *(const float4*)(A0 + k0 + 16);
            a1 = *(const float4*)(A1 + k0 + 16);
            b0 = *(const float4*)(B0 + (size_t)(k0 + 16) * DM);
            b1 = *(const float4*)(B1 + (size_t)(k0 + 16) * DM);
        }
        #pragma unroll
        for (int kk = 0; kk < 16; kk++) {
            float4 aA = *(const float4*)&As[buf][kk][ty * 4];
            float4 aB = *(const float4*)&As[buf][kk][64 + ty * 4];
            float4 bA = *(const float4*)&Bs[buf][kk][tx * 4];
            float4 bB = *(const float4*)&Bs[buf][kk][64 + tx * 4];
            float ar[8] = {aA.x, aA.y, aA.z, aA.w, aB.x, aB.y, aB.z, aB.w};
            float br[8] = {bA.x, bA.y, bA.z, bA.w, bB.x, bB.y, bB.z, bB.w};
            #pragma unroll
            for (int i = 0; i < 8; i++)
                #pragma unroll
                for (int j = 0; j < 8; j++)
                    acc[i][j] += ar[i] * br[j];
        }
        if (more) {
            int nb = buf ^ 1;
            As[nb][ac0 + 0][ar0] = a0.x; As[nb][ac0 + 1][ar0] = a0.y;
            As[nb][ac0 + 2][ar0] = a0.z; As[nb][ac0 + 3][ar0] = a0.w;
            As[nb][ac1 + 0][ar1] = a1.x; As[nb][ac1 + 1][ar1] = a1.y;
            As[nb][ac1 + 2][ar1] = a1.z; As[nb][ac1 + 3][ar1] = a1.w;
            *(float4*)&Bs[nb][brw0][bc0] = b0;
            *(float4*)&Bs[nb][brw1][bc1] = b1;
            __syncthreads();
            buf = nb;
        }
    }

    #pragma unroll
    for (int ig = 0; ig < 2; ig++) {
        #pragma unroll
        for (int i = 0; i < 4; i++) {
            int ai = ig * 4 + i;
            float* crow = C + (size_t)(m0 + ig * 64 + ty * 4 + i) * DM + n0;
            *(float4*)(crow + tx * 4) =
                make_float4(acc[ai][0], acc[ai][1], acc[ai][2], acc[ai][3]);
            *(float4*)(crow + 64 + tx * 4) =
                make_float4(acc[ai][4], acc[ai][5], acc[ai][6], acc[ai][7]);
        }
    }
}

// ---------------------------------------------------------------------------
// Kernel 2: RoPE (in place on g_Q, g_K) with b_rotate elementwise scaling.
// ---------------------------------------------------------------------------
__global__ void rope_kernel()
{
    int t = blockIdx.x * blockDim.x + threadIdx.x;   // 0 .. SEQ*NH*32-1
    int i = t & 31;
    int h = (t >> 5) & 15;
    int n = t >> 9;
    if (n >= SEQ) return;

    float inv = (float)exp(-(double)i * (9.210340371976184 / 32.0)); // ln(1e4)/32
    float ang = (float)n * inv;
    float sa, ca;
    sincosf(ang, &sa, &ca);

    size_t base = (size_t)n * DM + h * DK + 2 * i;
    float br0 = g_BR[base], br1 = g_BR[base + 1];

    float q0 = g_Q[base], q1 = g_Q[base + 1];
    g_Q[base]     = (q0 * ca - q1 * sa) * br0;
    g_Q[base + 1] = (q0 * sa + q1 * ca) * br1;

    float k0 = g_K[base], k1 = g_K[base + 1];
    g_K[base]     = (k0 * ca - k1 * sa) * br0;
    g_K[base + 1] = (k0 * sa + k1 * ca) * br1;
}

// ---------------------------------------------------------------------------
// Kernel 3: flash attention (fp32, online softmax).
// Grid (SEQ/64, NH); 128 threads; 2 threads per q-row (d split 32/32),
// partial scores combined with shfl_xor(1). BN=32 K/V tile in smem.
// ---------------------------------------------------------------------------
__global__ __launch_bounds__(128) void attn_kernel(
    const unsigned int* __restrict__ mask, float* __restrict__ out)
{
    int h = blockIdx.y;
    int tid = threadIdx.x;
    int row = tid >> 1;          // 0..63
    int c = tid & 1;             // which 32-dim half
    int r = blockIdx.x * 64 + row;

    __shared__ float ks[32][64];
    __shared__ float vs[32][64];
    __shared__ unsigned char mk[SEQ];

    for (int i = tid; i < SEQ; i += 128)
        mk[i] = (mask[i] != 0u) ? 1 : 0;

    float q[32];
    {
        const float4* qp = (const float4*)(g_Q + (size_t)r * DM + h * DK + c * 32);
        #pragma unroll
        for (int i = 0; i < 8; i++) {
            float4 v = qp[i];
            q[4 * i] = v.x; q[4 * i + 1] = v.y; q[4 * i + 2] = v.z; q[4 * i + 3] = v.w;
        }
    }
    bool mr = (mask[r] != 0u);

    float o[32];
    #pragma unroll
    for (int d = 0; d < 32; d++) o[d] = 0.f;
    float m = -INFINITY, l = 0.f;
    __syncthreads();

    const float4* Kb = (const float4*)g_K;
    const float4* Vb = (const float4*)g_V;

    for (int k0 = 0; k0 < SEQ; k0 += 32) {
        // load K/V tiles: 32 rows x 64 floats = 512 float4 each, 4 per thread
        #pragma unroll
        for (int u = 0; u < 4; u++) {
            int f = tid + u * 128;              // 0..511
            int j = f >> 4, d4 = f & 15;
            size_t gi = (size_t)(k0 + j) * (DM / 4) + h * (DK / 4) + d4;
            ((float4*)ks)[f] = Kb[gi];
            ((float4*)vs)[f] = Vb[gi];
        }
        __syncthreads();

        // partial scores over this thread's 32 dims
        float s[32];
        #pragma unroll
        for (int j = 0; j < 32; j++) s[j] = 0.f;
        #pragma unroll
        for (int d4 = 0; d4 < 8; d4++) {
            float qa = q[4 * d4 + 0], qb = q[4 * d4 + 1];
            float qc = q[4 * d4 + 2], qd = q[4 * d4 + 3];
            #pragma unroll
            for (int j = 0; j < 32; j++) {
                float4 kv = *(const float4*)&ks[j][c * 32 + d4 * 4];
                s[j] += qa * kv.x + qb * kv.y + qc * kv.z + qd * kv.w;
            }
        }
        // combine halves (lane pair)
        #pragma unroll
        for (int j = 0; j < 32; j++)
            s[j] += __shfl_xor_sync(0xffffffffu, s[j], 1);

        // mask + online softmax update
        float tm = -INFINITY;
        #pragma unroll
        for (int j = 0; j < 32; j++) {
            bool ok = mr && mk[k0 + j];
            s[j] = ok ? s[j] * 0.125f : -1e30f;
            tm = fmaxf(tm, s[j]);
        }
        float mnew = fmaxf(m, tm);
        float scale = __expf(m - mnew);
        float ps = 0.f;
        #pragma unroll
        for (int j = 0; j < 32; j++) { s[j] = __expf(s[j] - mnew); ps += s[j]; }
        l = l * scale + ps;
        #pragma unroll
        for (int d = 0; d < 32; d++) o[d] *= scale;

        // o += p @ V (this thread's 32 dims)
        #pragma unroll
        for (int j = 0; j < 32; j++) {
            float pj = s[j];
            #pragma unroll
            for (int d4 = 0; d4 < 8; d4++) {
                float4 vv = *(const float4*)&vs[j][c * 32 + d4 * 4];
                o[4 * d4 + 0] += pj * vv.x;
                o[4 * d4 + 1] += pj * vv.y;
                o[4 * d4 + 2] += pj * vv.z;
                o[4 * d4 + 3] += pj * vv.w;
            }
        }
        m = mnew;
        __syncthreads();
    }

    float invl = 1.f / l;
    float4* op = (float4*)(out + (size_t)r * DM + h * DK + c * 32);
    #pragma unroll
    for (int d4 = 0; d4 < 8; d4++) {
        op[d4] = make_float4(o[4 * d4] * invl, o[4 * d4 + 1] * invl,
                             o[4 * d4 + 2] * invl, o[4 * d4 + 3] * invl);
    }
}

// ---------------------------------------------------------------------------
extern "C" void kernel_launch(void* const* d_in, const int* in_sizes, int n_in,
                              void* d_out, int out_size)
{
    const float* query = (const float*)d_in[0];
    const float* key   = (const float*)d_in[1];
    const float* value = (const float*)d_in[2];
    const float* bemb  = (const float*)d_in[3];
    const unsigned int* mask = (const unsigned int*)d_in[4];
    const float* LL    = (const float*)d_in[5];
    const float* bproj = (const float*)d_in[6];
    float* out = (float*)d_out;

    dim3 gg(DM / 128, SEQ / 128, 4);
    proj_gemm<<<gg, 256>>>(query, key, value, bemb, LL, bproj);

    rope_kernel<<<(SEQ * NH * 32) / 256, 256>>>();

    dim3 ga(SEQ / 64, NH);
    attn_kernel<<<ga, 128>>>(mask, out);
}

// round 4
// speedup vs baseline: 1.2737x; 1.2737x over previous
#include <cuda_runtime.h>
#include <math.h>

#define SEQ 2048
#define DM 1024
#define NH 16
#define DK 64

// Scratch (static device globals — no runtime allocation allowed)
__device__ float g_Q[SEQ * DM];
__device__ float g_K[SEQ * DM];
__device__ float g_V[SEQ * DM];
__device__ float g_BR[SEQ * DM];

// ---------------------------------------------------------------------------
// Kernel 1: batched projection GEMM.  C[n][h*64+k] = sum_d X[n][d] * W[d][...]
// z = 0:Q, 1:K, 2:V, 3:b_rotate.
// 128x128 tile, 256 threads, 8x8 micro-tile, BK=16, double-buffered smem.
// ---------------------------------------------------------------------------
__global__ __launch_bounds__(256, 2) void proj_gemm(
    const float* __restrict__ query, const float* __restrict__ key,
    const float* __restrict__ value, const float* __restrict__ bemb,
    const float* __restrict__ LL, const float* __restrict__ bproj)
{
    int z = blockIdx.z;
    const float* X = (z == 0) ? query : (z == 1) ? key : (z == 2) ? value : bemb;
    const float* W = (z < 3) ? (LL + (size_t)z * DM * DM) : bproj;
    float* C = (z == 0) ? g_Q : (z == 1) ? g_K : (z == 2) ? g_V : g_BR;

    __shared__ float As[2][16][128];   // [buf][k][m]  (A transposed)
    __shared__ float Bs[2][16][128];   // [buf][k][n]

    int tid = threadIdx.x;
    int tx = tid & 15, ty = tid >> 4;
    int m0 = blockIdx.y * 128, n0 = blockIdx.x * 128;

    // A tile: 128 rows x 16 cols = 512 float4; thread handles f=tid, tid+256
    int ar0 = tid >> 2,         ac0 = (tid & 3) * 4;
    int ar1 = (tid + 256) >> 2, ac1 = ((tid + 256) & 3) * 4;
    // B tile: 16 rows x 128 cols = 512 float4
    int brw0 = tid >> 5,         bc0 = (tid & 31) * 4;
    int brw1 = (tid + 256) >> 5, bc1 = ((tid + 256) & 31) * 4;

    const float* A0 = X + (size_t)(m0 + ar0) * DM + ac0;
    const float* A1 = X + (size_t)(m0 + ar1) * DM + ac1;
    const float* B0 = W + (size_t)brw0 * DM + n0 + bc0;
    const float* B1 = W + (size_t)brw1 * DM + n0 + bc1;

    float4 a0 = *(const float4*)(A0);
    float4 a1 = *(const float4*)(A1);
    float4 b0 = *(const float4*)(B0);
    float4 b1 = *(const float4*)(B1);

    As[0][ac0 + 0][ar0] = a0.x; As[0][ac0 + 1][ar0] = a0.y;
    As[0][ac0 + 2][ar0] = a0.z; As[0][ac0 + 3][ar0] = a0.w;
    As[0][ac1 + 0][ar1] = a1.x; As[0][ac1 + 1][ar1] = a1.y;
    As[0][ac1 + 2][ar1] = a1.z; As[0][ac1 + 3][ar1] = a1.w;
    *(float4*)&Bs[0][brw0][bc0] = b0;
    *(float4*)&Bs[0][brw1][bc1] = b1;
    __syncthreads();

    float acc[8][8] = {};
    int buf = 0;

    for (int k0 = 0; k0 < DM; k0 += 16) {
        bool more = (k0 + 16) < DM;
        if (more) {
            a0 = *(const float4*)(A0 + k0 + 16);
            a1 = *(const float4*)(A1 + k0 + 16);
            b0 = *(const float4*)(B0 + (size_t)(k0 + 16) * DM);
            b1 = *(const float4*)(B1 + (size_t)(k0 + 16) * DM);
        }
        #pragma unroll
        for (int kk = 0; kk < 16; kk++) {
            float4 aA = *(const float4*)&As[buf][kk][ty * 4];
            float4 aB = *(const float4*)&As[buf][kk][64 + ty * 4];
            float4 bA = *(const float4*)&Bs[buf][kk][tx * 4];
            float4 bB = *(const float4*)&Bs[buf][kk][64 + tx * 4];
            float ar[8] = {aA.x, aA.y, aA.z, aA.w, aB.x, aB.y, aB.z, aB.w};
            float br[8] = {bA.x, bA.y, bA.z, bA.w, bB.x, bB.y, bB.z, bB.w};
            #pragma unroll
            for (int i = 0; i < 8; i++)
                #pragma unroll
                for (int j = 0; j < 8; j++)
                    acc[i][j] += ar[i] * br[j];
        }
        if (more) {
            int nb = buf ^ 1;
            As[nb][ac0 + 0][ar0] = a0.x; As[nb][ac0 + 1][ar0] = a0.y;
            As[nb][ac0 + 2][ar0] = a0.z; As[nb][ac0 + 3][ar0] = a0.w;
            As[nb][ac1 + 0][ar1] = a1.x; As[nb][ac1 + 1][ar1] = a1.y;
            As[nb][ac1 + 2][ar1] = a1.z; As[nb][ac1 + 3][ar1] = a1.w;
            *(float4*)&Bs[nb][brw0][bc0] = b0;
            *(float4*)&Bs[nb][brw1][bc1] = b1;
            __syncthreads();
            buf = nb;
        }
    }

    #pragma unroll
    for (int ig = 0; ig < 2; ig++) {
        #pragma unroll
        for (int i = 0; i < 4; i++) {
            int ai = ig * 4 + i;
            float* crow = C + (size_t)(m0 + ig * 64 + ty * 4 + i) * DM + n0;
            *(float4*)(crow + tx * 4) =
                make_float4(acc[ai][0], acc[ai][1], acc[ai][2], acc[ai][3]);
            *(float4*)(crow + 64 + tx * 4) =
                make_float4(acc[ai][4], acc[ai][5], acc[ai][6], acc[ai][7]);
        }
    }
}

// ---------------------------------------------------------------------------
// Kernel 2: RoPE (in place on g_Q, g_K) with b_rotate elementwise scaling.
// ---------------------------------------------------------------------------
__global__ void rope_kernel()
{
    int t = blockIdx.x * blockDim.x + threadIdx.x;   // 0 .. SEQ*NH*32-1
    int i = t & 31;
    int h = (t >> 5) & 15;
    int n = t >> 9;
    if (n >= SEQ) return;

    float inv = (float)exp(-(double)i * (9.210340371976184 / 32.0)); // ln(1e4)/32
    float ang = (float)n * inv;
    float sa, ca;
    sincosf(ang, &sa, &ca);

    size_t base = (size_t)n * DM + h * DK + 2 * i;
    float br0 = g_BR[base], br1 = g_BR[base + 1];

    float q0 = g_Q[base], q1 = g_Q[base + 1];
    g_Q[base]     = (q0 * ca - q1 * sa) * br0;
    g_Q[base + 1] = (q0 * sa + q1 * ca) * br1;

    float k0 = g_K[base], k1 = g_K[base + 1];
    g_K[base]     = (k0 * ca - k1 * sa) * br0;
    g_K[base + 1] = (k0 * sa + k1 * ca) * br1;
}

// ---------------------------------------------------------------------------
// Kernel 3: flash attention (fp32, online softmax).
// Grid (SEQ/64, NH); 64 threads; one thread per q-row (broadcast-LDS design:
// every lane of a warp reads the SAME ks/vs address -> conflict-free).
// BN=16 K/V tile in smem.
// ---------------------------------------------------------------------------
__global__ __launch_bounds__(64, 5) void attn_kernel(
    const unsigned int* __restrict__ mask, float* __restrict__ out)
{
    int h = blockIdx.y;
    int tid = threadIdx.x;
    int r = blockIdx.x * 64 + tid;

    __shared__ float ks[16][64];
    __shared__ float vs[16][64];
    __shared__ unsigned char mk[SEQ];

    for (int i = tid; i < SEQ; i += 64)
        mk[i] = (mask[i] != 0u) ? 1 : 0;

    float q[64];
    {
        const float4* qp = (const float4*)(g_Q + (size_t)r * DM + h * DK);
        #pragma unroll
        for (int i = 0; i < 16; i++) {
            float4 v = qp[i];
            q[4 * i] = v.x; q[4 * i + 1] = v.y; q[4 * i + 2] = v.z; q[4 * i + 3] = v.w;
        }
    }
    bool mr = (mask[r] != 0u);

    float o[64];
    #pragma unroll
    for (int d = 0; d < 64; d++) o[d] = 0.f;
    float m = -INFINITY, l = 0.f;
    __syncthreads();

    const float4* Kb = (const float4*)g_K;
    const float4* Vb = (const float4*)g_V;

    for (int k0 = 0; k0 < SEQ; k0 += 16) {
        // Cooperative load of K/V tiles: 16 rows x 16 float4 = 256 float4 each
        #pragma unroll
        for (int u = 0; u < 4; u++) {
            int f = tid + u * 64;          // 0..255
            int j = f >> 4, d4 = f & 15;
            size_t gi = (size_t)(k0 + j) * (DM / 4) + h * (DK / 4) + d4;
            ((float4*)ks)[f] = Kb[gi];
            ((float4*)vs)[f] = Vb[gi];
        }
        __syncthreads();

        // scores: 16 independent accumulator chains; ks reads are warp-broadcast
        float s[16];
        #pragma unroll
        for (int j = 0; j < 16; j++) s[j] = 0.f;
        #pragma unroll
        for (int d4 = 0; d4 < 16; d4++) {
            float qa = q[4 * d4 + 0], qb = q[4 * d4 + 1];
            float qc = q[4 * d4 + 2], qd = q[4 * d4 + 3];
            #pragma unroll
            for (int j = 0; j < 16; j++) {
                float4 kv = *(const float4*)&ks[j][d4 * 4];   // broadcast
                s[j] += qa * kv.x + qb * kv.y + qc * kv.z + qd * kv.w;
            }
        }

        // mask + online softmax update
        float tm = -INFINITY;
        #pragma unroll
        for (int j = 0; j < 16; j++) {
            bool ok = mr && mk[k0 + j];
            s[j] = ok ? s[j] * 0.125f : -1e30f;
            tm = fmaxf(tm, s[j]);
        }
        float mnew = fmaxf(m, tm);
        float scale = __expf(m - mnew);   // m=-inf first iter -> 0
        float ps = 0.f;
        #pragma unroll
        for (int j = 0; j < 16; j++) { s[j] = __expf(s[j] - mnew); ps += s[j]; }
        l = l * scale + ps;
        #pragma unroll
        for (int d = 0; d < 64; d++) o[d] *= scale;

        // o += p @ V
        #pragma unroll
        for (int j = 0; j < 16; j++) {
            float pj = s[j];
            #pragma unroll
            for (int d4 = 0; d4 < 16; d4++) {
                float4 vv = *(const float4*)&vs[j][d4 * 4];   // broadcast
                o[4 * d4 + 0] += pj * vv.x;
                o[4 * d4 + 1] += pj * vv.y;
                o[4 * d4 + 2] += pj * vv.z;
                o[4 * d4 + 3] += pj * vv.w;
            }
        }
        m = mnew;
        __syncthreads();
    }

    float invl = 1.f / l;
    float4* op = (float4*)(out + (size_t)r * DM + h * DK);
    #pragma unroll
    for (int d4 = 0; d4 < 16; d4++) {
        op[d4] = make_float4(o[4 * d4] * invl, o[4 * d4 + 1] * invl,
                             o[4 * d4 + 2] * invl, o[4 * d4 + 3] * invl);
    }
}

// ---------------------------------------------------------------------------
extern "C" void kernel_launch(void* const* d_in, const int* in_sizes, int n_in,
                              void* d_out, int out_size)
{
    const float* query = (const float*)d_in[0];
    const float* key   = (const float*)d_in[1];
    const float* value = (const float*)d_in[2];
    const float* bemb  = (const float*)d_in[3];
    const unsigned int* mask = (const unsigned int*)d_in[4];
    const float* LL    = (const float*)d_in[5];
    const float* bproj = (const float*)d_in[6];
    float* out = (float*)d_out;

    dim3 gg(DM / 128, SEQ / 128, 4);
    proj_gemm<<<gg, 256>>>(query, key, value, bemb, LL, bproj);

    rope_kernel<<<(SEQ * NH * 32) / 256, 256>>>();

    dim3 ga(SEQ / 64, NH);
    attn_kernel<<<ga, 64>>>(mask, out);
}

// round 7
// speedup vs baseline: 1.7214x; 1.3515x over previous
#include <cuda_runtime.h>
#include <cuda_bf16.h>
#include <math.h>
#include <stdint.h>

#define SEQ 2048
#define DM 1024
#define NH 16
#define DK 64

// fp32 results of projections (attention consumes these)
__device__ float g_Q[SEQ * DM];
__device__ float g_K[SEQ * DM];
__device__ float g_V[SEQ * DM];
__device__ float g_BR[SEQ * DM];

// split-bf16 operands: inputs [4][SEQ][DM], weights transposed [4][n=DM][k=DM]
__device__ __nv_bfloat16 g_Xhi[4 * SEQ * DM];
__device__ __nv_bfloat16 g_Xlo[4 * SEQ * DM];
__device__ __nv_bfloat16 g_Whi[4 * DM * DM];
__device__ __nv_bfloat16 g_Wlo[4 * DM * DM];

__device__ __forceinline__ uint32_t smem_u32(const void* p) {
    uint32_t a;
    asm("{ .reg .u64 t; cvta.to.shared.u64 t, %1; cvt.u32.u64 %0, t; }"
        : "=r"(a) : "l"(p));
    return a;
}

__device__ __forceinline__ void ldm_x4(uint32_t r[4], uint32_t addr) {
    asm volatile("ldmatrix.sync.aligned.m8n8.x4.shared.b16 {%0,%1,%2,%3}, [%4];"
                 : "=r"(r[0]), "=r"(r[1]), "=r"(r[2]), "=r"(r[3]) : "r"(addr));
}

__device__ __forceinline__ void mma_bf16(float c[4], const uint32_t a[4],
                                         const uint32_t* b) {
    asm volatile(
        "mma.sync.aligned.m16n8k16.row.col.f32.bf16.bf16.f32 "
        "{%0,%1,%2,%3}, {%4,%5,%6,%7}, {%8,%9}, {%0,%1,%2,%3};"
        : "+f"(c[0]), "+f"(c[1]), "+f"(c[2]), "+f"(c[3])
        : "r"(a[0]), "r"(a[1]), "r"(a[2]), "r"(a[3]), "r"(b[0]), "r"(b[1]));
}

// ---------------------------------------------------------------------------
// conv_x: fp32 inputs -> hi/lo bf16, layout unchanged [4][SEQ][DM]
// ---------------------------------------------------------------------------
__global__ __launch_bounds__(256) void conv_x(
    const float* __restrict__ q, const float* __restrict__ k,
    const float* __restrict__ v, const float* __restrict__ b)
{
    const int PER = SEQ * DM / 4;               // float4 per tensor
    int t = blockIdx.x * 256 + threadIdx.x;     // 0 .. 4*PER-1
    int z = t / PER, i = t - z * PER;
    const float* src = (z == 0) ? q : (z == 1) ? k : (z == 2) ? v : b;
    float4 x = ((const float4*)src)[i];

    __nv_bfloat16 h0 = __float2bfloat16(x.x), h1 = __float2bfloat16(x.y);
    __nv_bfloat16 h2 = __float2bfloat16(x.z), h3 = __float2bfloat16(x.w);
    __nv_bfloat162 hA = {h0, h1}, hB = {h2, h3};
    __nv_bfloat162 lA = {__float2bfloat16(x.x - __bfloat162float(h0)),
                         __float2bfloat16(x.y - __bfloat162float(h1))};
    __nv_bfloat162 lB = {__float2bfloat16(x.z - __bfloat162float(h2)),
                         __float2bfloat16(x.w - __bfloat162float(h3))};
    size_t o = (size_t)z * SEQ * DM + (size_t)i * 4;
    *(uint2*)(g_Xhi + o) = make_uint2(*(uint32_t*)&hA, *(uint32_t*)&hB);
    *(uint2*)(g_Xlo + o) = make_uint2(*(uint32_t*)&lA, *(uint32_t*)&lB);
}

// ---------------------------------------------------------------------------
// conv_w: fp32 weights W[k][n] -> transposed hi/lo bf16 WT[n][k], 32x32 tiles
// ---------------------------------------------------------------------------
__global__ __launch_bounds__(256) void conv_w(
    const float* __restrict__ LL, const float* __restrict__ bproj)
{
    int z = blockIdx.z;
    const float* W = (z < 3) ? (LL + (size_t)z * DM * DM) : bproj;
    int k0 = blockIdx.y * 32, n0 = blockIdx.x * 32;

    __shared__ float tile[32][33];
    int tid = threadIdx.x;
    #pragma unroll
    for (int i = 0; i < 4; i++) {
        int f = tid + i * 256, r = f >> 5, c = f & 31;
        tile[r][c] = W[(size_t)(k0 + r) * DM + n0 + c];
    }
    __syncthreads();
    #pragma unroll
    for (int i = 0; i < 4; i++) {
        int f = tid + i * 256, r = f >> 5, c = f & 31;   // r: n, c: k
        float x = tile[c][r];
        __nv_bfloat16 h = __float2bfloat16(x);
        size_t o = (size_t)z * DM * DM + (size_t)(n0 + r) * DM + k0 + c;
        g_Whi[o] = h;
        g_Wlo[o] = __float2bfloat16(x - __bfloat162float(h));
    }
}

// ---------------------------------------------------------------------------
// proj_mma: C = X @ W via mma.sync bf16, 4 cross-products (hi/lo split).
// BM=128, BN=128, BK=32, 256 thr, 8 warps (4 m x 2 n), warp tile 32x64.
// smem k-stride 40 elems (80B) -> conflict-free ldmatrix.
// ---------------------------------------------------------------------------
#define SAS 40

__global__ __launch_bounds__(256) void proj_mma()
{
    __shared__ __nv_bfloat16 sAh[128 * SAS], sAl[128 * SAS];
    __shared__ __nv_bfloat16 sBh[128 * SAS], sBl[128 * SAS];

    int z = blockIdx.z;
    int m0 = blockIdx.y * 128, n0 = blockIdx.x * 128;
    const __nv_bfloat16* Ah = g_Xhi + (size_t)z * SEQ * DM;
    const __nv_bfloat16* Al = g_Xlo + (size_t)z * SEQ * DM;
    const __nv_bfloat16* Bh = g_Whi + (size_t)z * DM * DM;
    const __nv_bfloat16* Bl = g_Wlo + (size_t)z * DM * DM;
    float* C = (z == 0) ? g_Q : (z == 1) ? g_K : (z == 2) ? g_V : g_BR;

    int tid = threadIdx.x, lane = tid & 31, wid = tid >> 5;
    int wm = wid & 3, wn = wid >> 2;            // warp m 0-3, n 0-1

    // loader mapping: 2048 b32 per tile, 8 per thread; row=f>>4, colb32=f&15
    int lrow[8], lcol[8];
    #pragma unroll
    for (int i = 0; i < 8; i++) { int f = i * 256 + tid; lrow[i] = f >> 4; lcol[i] = (f & 15) * 2; }

    uint32_t pAh[8], pAl[8], pBh[8], pBl[8];
    #pragma unroll
    for (int i = 0; i < 8; i++) {
        size_t oa = (size_t)(m0 + lrow[i]) * DM + lcol[i];
        size_t ob = (size_t)(n0 + lrow[i]) * DM + lcol[i];
        pAh[i] = *(const uint32_t*)(Ah + oa);
        pAl[i] = *(const uint32_t*)(Al + oa);
        pBh[i] = *(const uint32_t*)(Bh + ob);
        pBl[i] = *(const uint32_t*)(Bl + ob);
    }

    float acc[2][8][4];
    #pragma unroll
    for (int mt = 0; mt < 2; mt++)
        #pragma unroll
        for (int nt = 0; nt < 8; nt++)
            #pragma unroll
            for (int e = 0; e < 4; e++) acc[mt][nt][e] = 0.f;

    uint32_t sa_h = smem_u32(sAh), sa_l = smem_u32(sAl);
    uint32_t sb_h = smem_u32(sBh), sb_l = smem_u32(sBl);
    // ldmatrix lane address offsets (in elements)
    int aoff = (wm * 32 + (lane & 15)) * SAS + (lane >> 4) * 8;
    int boff = (wn * 64 + ((lane >> 4) & 1) * 8 + (lane & 7)) * SAS + ((lane >> 3) & 1) * 8;

    const int NCH = DM / 32;
    for (int c = 0; c < NCH; c++) {
        // store prefetched chunk
        #pragma unroll
        for (int i = 0; i < 8; i++) {
            int so = lrow[i] * SAS + lcol[i];
            *(uint32_t*)(sAh + so) = pAh[i];
            *(uint32_t*)(sAl + so) = pAl[i];
            *(uint32_t*)(sBh + so) = pBh[i];
            *(uint32_t*)(sBl + so) = pBl[i];
        }
        __syncthreads();

        if (c + 1 < NCH) {
            int k0 = (c + 1) * 32;
            #pragma unroll
            for (int i = 0; i < 8; i++) {
                size_t oa = (size_t)(m0 + lrow[i]) * DM + k0 + lcol[i];
                size_t ob = (size_t)(n0 + lrow[i]) * DM + k0 + lcol[i];
                pAh[i] = *(const uint32_t*)(Ah + oa);
                pAl[i] = *(const uint32_t*)(Al + oa);
                pBh[i] = *(const uint32_t*)(Bh + ob);
                pBl[i] = *(const uint32_t*)(Bl + ob);
            }
        }

        #pragma unroll
        for (int ks = 0; ks < 2; ks++) {
            uint32_t ah[2][4], al[2][4];
            #pragma unroll
            for (int mt = 0; mt < 2; mt++) {
                uint32_t off = (uint32_t)(aoff + mt * 16 * SAS + ks * 16) * 2;
                ldm_x4(ah[mt], sa_h + off);
                ldm_x4(al[mt], sa_l + off);
            }
            uint32_t bh[4][4], bl[4][4];   // [npair][4]: regs 0,1 = nt even; 2,3 = nt odd
            #pragma unroll
            for (int np = 0; np < 4; np++) {
                uint32_t off = (uint32_t)(boff + np * 16 * SAS + ks * 16) * 2;
                ldm_x4(bh[np], sb_h + off);
                ldm_x4(bl[np], sb_l + off);
            }
            #pragma unroll
            for (int mt = 0; mt < 2; mt++)
                #pragma unroll
                for (int nt = 0; nt < 8; nt++) {
                    const uint32_t* Bhf = &bh[nt >> 1][(nt & 1) * 2];
                    const uint32_t* Blf = &bl[nt >> 1][(nt & 1) * 2];
                    mma_bf16(acc[mt][nt], ah[mt], Bhf);
                    mma_bf16(acc[mt][nt], ah[mt], Blf);
                    mma_bf16(acc[mt][nt], al[mt], Bhf);
                    mma_bf16(acc[mt][nt], al[mt], Blf);
                }
        }
        __syncthreads();
    }

    // epilogue: c0,c1 at (m, n..n+1); c2,c3 at (m+8, n..n+1)
    int mbase = m0 + wm * 32 + (lane >> 2);
    int nbase = n0 + wn * 64 + (lane & 3) * 2;
    #pragma unroll
    for (int mt = 0; mt < 2; mt++)
        #pragma unroll
        for (int nt = 0; nt < 8; nt++) {
            int mm = mbase + mt * 16, nn = nbase + nt * 8;
            *(float2*)(C + (size_t)mm * DM + nn) =
                make_float2(acc[mt][nt][0], acc[mt][nt][1]);
            *(float2*)(C + (size_t)(mm + 8) * DM + nn) =
                make_float2(acc[mt][nt][2], acc[mt][nt][3]);
        }
}

// ---------------------------------------------------------------------------
// rope: in place on g_Q, g_K with b_rotate scaling
// ---------------------------------------------------------------------------
__global__ void rope_kernel()
{
    int t = blockIdx.x * blockDim.x + threadIdx.x;
    int i = t & 31;
    int h = (t >> 5) & 15;
    int n = t >> 9;
    if (n >= SEQ) return;

    float inv = (float)exp(-(double)i * (9.210340371976184 / 32.0));
    float ang = (float)n * inv;
    float sa, ca;
    sincosf(ang, &sa, &ca);

    size_t base = (size_t)n * DM + h * DK + 2 * i;
    float br0 = g_BR[base], br1 = g_BR[base + 1];

    float q0 = g_Q[base], q1 = g_Q[base + 1];
    g_Q[base]     = (q0 * ca - q1 * sa) * br0;
    g_Q[base + 1] = (q0 * sa + q1 * ca) * br1;

    float k0 = g_K[base], k1 = g_K[base + 1];
    g_K[base]     = (k0 * ca - k1 * sa) * br0;
    g_K[base + 1] = (k0 * sa + k1 * ca) * br1;
}

// ---------------------------------------------------------------------------
// attn: fp32 flash attention, 256 thr (one q-row each, broadcast-LDS),
// BN=32 tile, pre-scaled q, lazy rescale.
// ---------------------------------------------------------------------------
__global__ __launch_bounds__(256) void attn_kernel(
    const unsigned int* __restrict__ mask, float* __restrict__ out)
{
    int h = blockIdx.y;
    int tid = threadIdx.x;
    int r = blockIdx.x * 256 + tid;

    __shared__ float ks[32][64];
    __shared__ float vs[32][64];
    __shared__ unsigned char mk[SEQ];

    for (int i = tid; i < SEQ; i += 256)
        mk[i] = (mask[i] != 0u) ? 1 : 0;

    float q[64];
    {
        const float4* qp = (const float4*)(g_Q + (size_t)r * DM + h * DK);
        #pragma unroll
        for (int i = 0; i < 16; i++) {
            float4 v = qp[i];
            q[4 * i]     = v.x * 0.125f;
            q[4 * i + 1] = v.y * 0.125f;
            q[4 * i + 2] = v.z * 0.125f;
            q[4 * i + 3] = v.w * 0.125f;
        }
    }
    bool mr = (mask[r] != 0u);

    float o[64];
    #pragma unroll
    for (int d = 0; d < 64; d++) o[d] = 0.f;
    float m = -INFINITY, l = 0.f;
    __syncthreads();

    const float4* Kb = (const float4*)g_K;
    const float4* Vb = (const float4*)g_V;

    for (int k0 = 0; k0 < SEQ; k0 += 32) {
        #pragma unroll
        for (int u = 0; u < 2; u++) {
            int f = tid + u * 256;
            int j = f >> 4, d4 = f & 15;
            size_t gi = (size_t)(k0 + j) * (DM / 4) + h * (DK / 4) + d4;
            ((float4*)ks)[f] = Kb[gi];
            ((float4*)vs)[f] = Vb[gi];
        }
        __syncthreads();

        float s[32];
        #pragma unroll
        for (int j = 0; j < 32; j++) s[j] = 0.f;
        #pragma unroll
        for (int d4 = 0; d4 < 16; d4++) {
            float qa = q[4 * d4 + 0], qb = q[4 * d4 + 1];
            float qc = q[4 * d4 + 2], qd = q[4 * d4 + 3];
            #pragma unroll
            for (int j = 0; j < 32; j++) {
                float4 kv = *(const float4*)&ks[j][d4 * 4];   // broadcast
                s[j] += qa * kv.x + qb * kv.y + qc * kv.z + qd * kv.w;
            }
        }

        float tm = -INFINITY;
        #pragma unroll
        for (int j = 0; j < 32; j++) {
            bool ok = mr && mk[k0 + j];
            s[j] = ok ? s[j] : -1e30f;
            tm = fmaxf(tm, s[j]);
        }
        if (tm > m) {
            float sc = __expf(m - tm);
            l *= sc;
            #pragma unroll
            for (int d = 0; d < 64; d++) o[d] *= sc;
            m = tm;
        }
        float ps = 0.f;
        #pragma unroll
        for (int j = 0; j < 32; j++) { s[j] = __expf(s[j] - m); ps += s[j]; }
        l += ps;

        #pragma unroll
        for (int j = 0; j < 32; j++) {
            float pj = s[j];
            #pragma unroll
            for (int d4 = 0; d4 < 16; d4++) {
                float4 vv = *(const float4*)&vs[j][d4 * 4];   // broadcast
                o[4 * d4 + 0] += pj * vv.x;
                o[4 * d4 + 1] += pj * vv.y;
                o[4 * d4 + 2] += pj * vv.z;
                o[4 * d4 + 3] += pj * vv.w;
            }
        }
        __syncthreads();
    }

    float invl = 1.f / l;
    float4* op = (float4*)(out + (size_t)r * DM + h * DK);
    #pragma unroll
    for (int d4 = 0; d4 < 16; d4++) {
        op[d4] = make_float4(o[4 * d4] * invl, o[4 * d4 + 1] * invl,
                             o[4 * d4 + 2] * invl, o[4 * d4 + 3] * invl);
    }
}

// ---------------------------------------------------------------------------
extern "C" void kernel_launch(void* const* d_in, const int* in_sizes, int n_in,
                              void* d_out, int out_size)
{
    const float* query = (const float*)d_in[0];
    const float* key   = (const float*)d_in[1];
    const float* value = (const float*)d_in[2];
    const float* bemb  = (const float*)d_in[3];
    const unsigned int* mask = (const unsigned int*)d_in[4];
    const float* LL    = (const float*)d_in[5];
    const float* bproj = (const float*)d_in[6];
    float* out = (float*)d_out;

    conv_x<<<4 * SEQ * DM / 4 / 256, 256>>>(query, key, value, bemb);
    conv_w<<<dim3(DM / 32, DM / 32, 4), 256>>>(LL, bproj);

    proj_mma<<<dim3(DM / 128, SEQ / 128, 4), 256>>>();

    rope_kernel<<<(SEQ * NH * 32) / 256, 256>>>();

    attn_kernel<<<dim3(SEQ / 256, NH), 256>>>(mask, out);
}

// round 8
// speedup vs baseline: 3.6992x; 2.1489x over previous
#include <cuda_runtime.h>
#include <cuda_bf16.h>
#include <math.h>
#include <stdint.h>

#define SEQ 2048
#define DM 1024
#define NH 16
#define DK 64

// fp32 intermediates
__device__ float g_Q[SEQ * DM];
__device__ float g_K[SEQ * DM];
__device__ float g_BR[SEQ * DM];

// split-bf16 operands: proj inputs [4][SEQ][DM]; after rope_split, z0 = Qsplit,
// z1 = Ksplit (attention operands). Weights transposed [4][n][k].
__device__ __nv_bfloat16 g_Xhi[4 * SEQ * DM];
__device__ __nv_bfloat16 g_Xlo[4 * SEQ * DM];
__device__ __nv_bfloat16 g_Whi[4 * DM * DM];
__device__ __nv_bfloat16 g_Wlo[4 * DM * DM];
// V split (written by proj epilogue z==2; no aliasing with proj inputs)
__device__ __nv_bfloat16 g_Vhi[SEQ * DM];
__device__ __nv_bfloat16 g_Vlo[SEQ * DM];

__device__ __forceinline__ uint32_t smem_u32(const void* p) {
    uint32_t a;
    asm("{ .reg .u64 t; cvta.to.shared.u64 t, %1; cvt.u32.u64 %0, t; }"
        : "=r"(a) : "l"(p));
    return a;
}
__device__ __forceinline__ void ldm_x4(uint32_t r[4], uint32_t addr) {
    asm volatile("ldmatrix.sync.aligned.m8n8.x4.shared.b16 {%0,%1,%2,%3}, [%4];"
                 : "=r"(r[0]), "=r"(r[1]), "=r"(r[2]), "=r"(r[3]) : "r"(addr));
}
__device__ __forceinline__ void ldm_x4t(uint32_t r[4], uint32_t addr) {
    asm volatile("ldmatrix.sync.aligned.m8n8.x4.trans.shared.b16 {%0,%1,%2,%3}, [%4];"
                 : "=r"(r[0]), "=r"(r[1]), "=r"(r[2]), "=r"(r[3]) : "r"(addr));
}
__device__ __forceinline__ void mma_bf16(float c[4], const uint32_t a[4],
                                         const uint32_t* b) {
    asm volatile(
        "mma.sync.aligned.m16n8k16.row.col.f32.bf16.bf16.f32 "
        "{%0,%1,%2,%3}, {%4,%5,%6,%7}, {%8,%9}, {%0,%1,%2,%3};"
        : "+f"(c[0]), "+f"(c[1]), "+f"(c[2]), "+f"(c[3])
        : "r"(a[0]), "r"(a[1]), "r"(a[2]), "r"(a[3]), "r"(b[0]), "r"(b[1]));
}
__device__ __forceinline__ uint32_t pack_bf16(float a, float b) {
    __nv_bfloat162 t = __floats2bfloat162_rn(a, b);
    return *(uint32_t*)&t;
}
__device__ __forceinline__ float bf2sum(uint32_t p) {
    __nv_bfloat162 b = *(__nv_bfloat162*)&p;
    return __bfloat162float(b.x) + __bfloat162float(b.y);
}

// ---------------------------------------------------------------------------
// conv_x: fp32 inputs -> hi/lo bf16 [4][SEQ][DM]
// ---------------------------------------------------------------------------
__global__ __launch_bounds__(256) void conv_x(
    const float* __restrict__ q, const float* __restrict__ k,
    const float* __restrict__ v, const float* __restrict__ b)
{
    const int PER = SEQ * DM / 4;
    int t = blockIdx.x * 256 + threadIdx.x;
    int z = t / PER, i = t - z * PER;
    const float* src = (z == 0) ? q : (z == 1) ? k : (z == 2) ? v : b;
    float4 x = ((const float4*)src)[i];

    __nv_bfloat16 h0 = __float2bfloat16(x.x), h1 = __float2bfloat16(x.y);
    __nv_bfloat16 h2 = __float2bfloat16(x.z), h3 = __float2bfloat16(x.w);
    __nv_bfloat162 hA = {h0, h1}, hB = {h2, h3};
    __nv_bfloat162 lA = {__float2bfloat16(x.x - __bfloat162float(h0)),
                         __float2bfloat16(x.y - __bfloat162float(h1))};
    __nv_bfloat162 lB = {__float2bfloat16(x.z - __bfloat162float(h2)),
                         __float2bfloat16(x.w - __bfloat162float(h3))};
    size_t o = (size_t)z * SEQ * DM + (size_t)i * 4;
    *(uint2*)(g_Xhi + o) = make_uint2(*(uint32_t*)&hA, *(uint32_t*)&hB);
    *(uint2*)(g_Xlo + o) = make_uint2(*(uint32_t*)&lA, *(uint32_t*)&lB);
}

// ---------------------------------------------------------------------------
// conv_w: fp32 weights W[k][n] -> transposed hi/lo bf16 WT[n][k]
// ---------------------------------------------------------------------------
__global__ __launch_bounds__(256) void conv_w(
    const float* __restrict__ LL, const float* __restrict__ bproj)
{
    int z = blockIdx.z;
    const float* W = (z < 3) ? (LL + (size_t)z * DM * DM) : bproj;
    int k0 = blockIdx.y * 32, n0 = blockIdx.x * 32;

    __shared__ float tile[32][33];
    int tid = threadIdx.x;
    #pragma unroll
    for (int i = 0; i < 4; i++) {
        int f = tid + i * 256, r = f >> 5, c = f & 31;
        tile[r][c] = W[(size_t)(k0 + r) * DM + n0 + c];
    }
    __syncthreads();
    #pragma unroll
    for (int i = 0; i < 4; i++) {
        int f = tid + i * 256, r = f >> 5, c = f & 31;
        float x = tile[c][r];
        __nv_bfloat16 h = __float2bfloat16(x);
        size_t o = (size_t)z * DM * DM + (size_t)(n0 + r) * DM + k0 + c;
        g_Whi[o] = h;
        g_Wlo[o] = __float2bfloat16(x - __bfloat162float(h));
    }
}

// ---------------------------------------------------------------------------
// proj_mma: C = X @ W, split-bf16, 4 cross-products.  z==2 writes V split.
// ---------------------------------------------------------------------------
#define SAS 40

__global__ __launch_bounds__(256) void proj_mma()
{
    __shared__ __nv_bfloat16 sAh[128 * SAS], sAl[128 * SAS];
    __shared__ __nv_bfloat16 sBh[128 * SAS], sBl[128 * SAS];

    int z = blockIdx.z;
    int m0 = blockIdx.y * 128, n0 = blockIdx.x * 128;
    const __nv_bfloat16* Ah = g_Xhi + (size_t)z * SEQ * DM;
    const __nv_bfloat16* Al = g_Xlo + (size_t)z * SEQ * DM;
    const __nv_bfloat16* Bh = g_Whi + (size_t)z * DM * DM;
    const __nv_bfloat16* Bl = g_Wlo + (size_t)z * DM * DM;
    float* C = (z == 0) ? g_Q : (z == 1) ? g_K : g_BR;   // z==2 handled below

    int tid = threadIdx.x, lane = tid & 31, wid = tid >> 5;
    int wm = wid & 3, wn = wid >> 2;

    int lrow[8], lcol[8];
    #pragma unroll
    for (int i = 0; i < 8; i++) { int f = i * 256 + tid; lrow[i] = f >> 4; lcol[i] = (f & 15) * 2; }

    uint32_t pAh[8], pAl[8], pBh[8], pBl[8];
    #pragma unroll
    for (int i = 0; i < 8; i++) {
        size_t oa = (size_t)(m0 + lrow[i]) * DM + lcol[i];
        size_t ob = (size_t)(n0 + lrow[i]) * DM + lcol[i];
        pAh[i] = *(const uint32_t*)(Ah + oa);
        pAl[i] = *(const uint32_t*)(Al + oa);
        pBh[i] = *(const uint32_t*)(Bh + ob);
        pBl[i] = *(const uint32_t*)(Bl + ob);
    }

    float acc[2][8][4];
    #pragma unroll
    for (int mt = 0; mt < 2; mt++)
        #pragma unroll
        for (int nt = 0; nt < 8; nt++)
            #pragma unroll
            for (int e = 0; e < 4; e++) acc[mt][nt][e] = 0.f;

    uint32_t sa_h = smem_u32(sAh), sa_l = smem_u32(sAl);
    uint32_t sb_h = smem_u32(sBh), sb_l = smem_u32(sBl);
    int aoff = (wm * 32 + (lane & 15)) * SAS + (lane >> 4) * 8;
    int boff = (wn * 64 + ((lane >> 4) & 1) * 8 + (lane & 7)) * SAS + ((lane >> 3) & 1) * 8;

    const int NCH = DM / 32;
    for (int c = 0; c < NCH; c++) {
        #pragma unroll
        for (int i = 0; i < 8; i++) {
            int so = lrow[i] * SAS + lcol[i];
            *(uint32_t*)(sAh + so) = pAh[i];
            *(uint32_t*)(sAl + so) = pAl[i];
            *(uint32_t*)(sBh + so) = pBh[i];
            *(uint32_t*)(sBl + so) = pBl[i];
        }
        __syncthreads();

        if (c + 1 < NCH) {
            int k0 = (c + 1) * 32;
            #pragma unroll
            for (int i = 0; i < 8; i++) {
                size_t oa = (size_t)(m0 + lrow[i]) * DM + k0 + lcol[i];
                size_t ob = (size_t)(n0 + lrow[i]) * DM + k0 + lcol[i];
                pAh[i] = *(const uint32_t*)(Ah + oa);
                pAl[i] = *(const uint32_t*)(Al + oa);
                pBh[i] = *(const uint32_t*)(Bh + ob);
                pBl[i] = *(const uint32_t*)(Bl + ob);
            }
        }

        #pragma unroll
        for (int ks = 0; ks < 2; ks++) {
            uint32_t ah[2][4], al[2][4];
            #pragma unroll
            for (int mt = 0; mt < 2; mt++) {
                uint32_t off = (uint32_t)(aoff + mt * 16 * SAS + ks * 16) * 2;
                ldm_x4(ah[mt], sa_h + off);
                ldm_x4(al[mt], sa_l + off);
            }
            uint32_t bh[4][4], bl[4][4];
            #pragma unroll
            for (int np = 0; np < 4; np++) {
                uint32_t off = (uint32_t)(boff + np * 16 * SAS + ks * 16) * 2;
                ldm_x4(bh[np], sb_h + off);
                ldm_x4(bl[np], sb_l + off);
            }
            #pragma unroll
            for (int mt = 0; mt < 2; mt++)
                #pragma unroll
                for (int nt = 0; nt < 8; nt++) {
                    const uint32_t* Bhf = &bh[nt >> 1][(nt & 1) * 2];
                    const uint32_t* Blf = &bl[nt >> 1][(nt & 1) * 2];
                    mma_bf16(acc[mt][nt], ah[mt], Bhf);
                    mma_bf16(acc[mt][nt], ah[mt], Blf);
                    mma_bf16(acc[mt][nt], al[mt], Bhf);
                    mma_bf16(acc[mt][nt], al[mt], Blf);
                }
        }
        __syncthreads();
    }

    int mbase = m0 + wm * 32 + (lane >> 2);
    int nbase = n0 + wn * 64 + (lane & 3) * 2;
    if (z == 2) {
        // V: write split-bf16 directly
        #pragma unroll
        for (int mt = 0; mt < 2; mt++)
            #pragma unroll
            for (int nt = 0; nt < 8; nt++) {
                int mm = mbase + mt * 16, nn = nbase + nt * 8;
                #pragma unroll
                for (int half = 0; half < 2; half++) {
                    float x = acc[mt][nt][half * 2], y = acc[mt][nt][half * 2 + 1];
                    float hx = __bfloat162float(__float2bfloat16(x));
                    float hy = __bfloat162float(__float2bfloat16(y));
                    size_t o = (size_t)(mm + half * 8) * DM + nn;
                    *(uint32_t*)(g_Vhi + o) = pack_bf16(x, y);
                    *(uint32_t*)(g_Vlo + o) = pack_bf16(x - hx, y - hy);
                }
            }
    } else {
        #pragma unroll
        for (int mt = 0; mt < 2; mt++)
            #pragma unroll
            for (int nt = 0; nt < 8; nt++) {
                int mm = mbase + mt * 16, nn = nbase + nt * 8;
                *(float2*)(C + (size_t)mm * DM + nn) =
                    make_float2(acc[mt][nt][0], acc[mt][nt][1]);
                *(float2*)(C + (size_t)(mm + 8) * DM + nn) =
                    make_float2(acc[mt][nt][2], acc[mt][nt][3]);
            }
    }
}

// ---------------------------------------------------------------------------
// rope_split: rope+b_rotate on fp32 q/k, fold q*0.125, write split-bf16
// Q -> g_Xhi/lo z0, K -> z1.
// ---------------------------------------------------------------------------
__global__ void rope_split()
{
    int t = blockIdx.x * blockDim.x + threadIdx.x;
    int i = t & 31;
    int h = (t >> 5) & 15;
    int n = t >> 9;
    if (n >= SEQ) return;

    float inv = (float)exp(-(double)i * (9.210340371976184 / 32.0));
    float ang = (float)n * inv;
    float sa, ca;
    sincosf(ang, &sa, &ca);

    size_t base = (size_t)n * DM + h * DK + 2 * i;
    float br0 = g_BR[base], br1 = g_BR[base + 1];

    float q0 = g_Q[base], q1 = g_Q[base + 1];
    float qr0 = (q0 * ca - q1 * sa) * br0 * 0.125f;
    float qr1 = (q0 * sa + q1 * ca) * br1 * 0.125f;

    float k0 = g_K[base], k1 = g_K[base + 1];
    float kr0 = (k0 * ca - k1 * sa) * br0;
    float kr1 = (k0 * sa + k1 * ca) * br1;

    float qh0 = __bfloat162float(__float2bfloat16(qr0));
    float qh1 = __bfloat162float(__float2bfloat16(qr1));
    float kh0 = __bfloat162float(__float2bfloat16(kr0));
    float kh1 = __bfloat162float(__float2bfloat16(kr1));

    *(uint32_t*)(g_Xhi + base) = pack_bf16(qr0, qr1);
    *(uint32_t*)(g_Xlo + base) = pack_bf16(qr0 - qh0, qr1 - qh1);
    *(uint32_t*)(g_Xhi + SEQ * DM + base) = pack_bf16(kr0, kr1);
    *(uint32_t*)(g_Xlo + SEQ * DM + base) = pack_bf16(kr0 - kh0, kr1 - kh1);
}

// ---------------------------------------------------------------------------
// attn_mma: flash attention on mma.sync.
// Grid (SEQ/256, NH), 512 thr / 16 warps, 16 q-rows per warp, BN=64.
// S: Q,K split (3 products). PV: P bf16 (l summed from rounded p), V split.
// ---------------------------------------------------------------------------
#define VS 72   // smem row stride (elems) for 64-wide tiles

__global__ __launch_bounds__(512) void attn_mma(
    const unsigned int* __restrict__ mask, float* __restrict__ out)
{
    extern __shared__ __align__(16) char dyn[];
    __nv_bfloat16* sQh = (__nv_bfloat16*)dyn;            // 256 x VS
    __nv_bfloat16* sQl = sQh + 256 * VS;
    __nv_bfloat16* sKh = sQl + 256 * VS;                 // 64 x VS
    __nv_bfloat16* sKl = sKh + 64 * VS;
    __nv_bfloat16* sVh = sKl + 64 * VS;
    __nv_bfloat16* sVl = sVh + 64 * VS;
    unsigned char* smk = (unsigned char*)(sVl + 64 * VS);

    int h = blockIdx.y, m0 = blockIdx.x * 256;
    int tid = threadIdx.x, lane = tid & 31, wid = tid >> 5;

    const __nv_bfloat16* Qh = g_Xhi;
    const __nv_bfloat16* Ql = g_Xlo;
    const __nv_bfloat16* Kh = g_Xhi + SEQ * DM;
    const __nv_bfloat16* Kl = g_Xlo + SEQ * DM;

    for (int i = tid; i < SEQ; i += 512)
        smk[i] = (mask[i] != 0u) ? 1 : 0;

    // stage Q hi/lo: 256 rows x 16 uint2 per array
    #pragma unroll
    for (int i = 0; i < 8; i++) {
        int f = tid + i * 512, row = f >> 4, c4 = f & 15;
        size_t g = (size_t)(m0 + row) * DM + h * DK + c4 * 4;
        *(uint2*)(sQh + row * VS + c4 * 4) = *(const uint2*)(Qh + g);
        *(uint2*)(sQl + row * VS + c4 * 4) = *(const uint2*)(Ql + g);
    }

    int r0 = m0 + wid * 16 + (lane >> 2);
    bool mr0 = (mask[r0] != 0u), mr1 = (mask[r0 + 8] != 0u);

    float mx0 = -INFINITY, mx1 = -INFINITY, l0 = 0.f, l1 = 0.f;
    float O[8][4];
    #pragma unroll
    for (int nt = 0; nt < 8; nt++)
        #pragma unroll
        for (int e = 0; e < 4; e++) O[nt][e] = 0.f;

    uint32_t sqh = smem_u32(sQh), sql = smem_u32(sQl);
    uint32_t skh = smem_u32(sKh), skl = smem_u32(sKl);
    uint32_t svh = smem_u32(sVh), svl = smem_u32(sVl);

    int qoff = (wid * 16 + (lane & 15)) * VS + (lane >> 4) * 8;
    int kboff = ((lane & 7) + ((lane >> 4) & 1) * 8) * VS + ((lane >> 3) & 1) * 8;
    int voff = (lane & 15) * VS + ((lane >> 4) & 1) * 8;

    __syncthreads();

    for (int kb = 0; kb < SEQ / 64; kb++) {
        // load K/V split tiles: 64 rows x 16 uint2 per array
        #pragma unroll
        for (int i = 0; i < 2; i++) {
            int f = tid + i * 512, row = f >> 4, c4 = f & 15;
            size_t g = (size_t)(kb * 64 + row) * DM + h * DK + c4 * 4;
            int so = row * VS + c4 * 4;
            *(uint2*)(sKh + so) = *(const uint2*)(Kh + g);
            *(uint2*)(sKl + so) = *(const uint2*)(Kl + g);
            *(uint2*)(sVh + so) = *(const uint2*)(g_Vhi + g);
            *(uint2*)(sVl + so) = *(const uint2*)(g_Vlo + g);
        }
        __syncthreads();

        // ---- S = Q K^T (3 products) ----
        float S[8][4];
        #pragma unroll
        for (int nt = 0; nt < 8; nt++)
            #pragma unroll
            for (int e = 0; e < 4; e++) S[nt][e] = 0.f;

        #pragma unroll
        for (int ks = 0; ks < 4; ks++) {
            uint32_t qh[4], ql[4];
            ldm_x4(qh, sqh + (uint32_t)(qoff + ks * 16) * 2);
            ldm_x4(ql, sql + (uint32_t)(qoff + ks * 16) * 2);
            #pragma unroll
            for (int np = 0; np < 4; np++) {
                uint32_t bh[4], bl[4];
                uint32_t off = (uint32_t)(kboff + np * 16 * VS + ks * 16) * 2;
                ldm_x4(bh, skh + off);
                ldm_x4(bl, skl + off);
                mma_bf16(S[2 * np],     qh, &bh[0]);
                mma_bf16(S[2 * np],     qh, &bl[0]);
                mma_bf16(S[2 * np],     ql, &bh[0]);
                mma_bf16(S[2 * np + 1], qh, &bh[2]);
                mma_bf16(S[2 * np + 1], qh, &bl[2]);
                mma_bf16(S[2 * np + 1], ql, &bh[2]);
            }
        }

        // ---- mask + online softmax ----
        float tm0 = -INFINITY, tm1 = -INFINITY;
        #pragma unroll
        for (int nt = 0; nt < 8; nt++) {
            int col = kb * 64 + nt * 8 + (lane & 3) * 2;
            bool c0 = smk[col] != 0, c1 = smk[col + 1] != 0;
            S[nt][0] = (mr0 && c0) ? S[nt][0] : -1e30f;
            S[nt][1] = (mr0 && c1) ? S[nt][1] : -1e30f;
            S[nt][2] = (mr1 && c0) ? S[nt][2] : -1e30f;
            S[nt][3] = (mr1 && c1) ? S[nt][3] : -1e30f;
            tm0 = fmaxf(tm0, fmaxf(S[nt][0], S[nt][1]));
            tm1 = fmaxf(tm1, fmaxf(S[nt][2], S[nt][3]));
        }
        tm0 = fmaxf(tm0, __shfl_xor_sync(0xffffffffu, tm0, 1));
        tm0 = fmaxf(tm0, __shfl_xor_sync(0xffffffffu, tm0, 2));
        tm1 = fmaxf(tm1, __shfl_xor_sync(0xffffffffu, tm1, 1));
        tm1 = fmaxf(tm1, __shfl_xor_sync(0xffffffffu, tm1, 2));

        if (tm0 > mx0) {
            float sc = __expf(mx0 - tm0);
            l0 *= sc;
            #pragma unroll
            for (int nt = 0; nt < 8; nt++) { O[nt][0] *= sc; O[nt][1] *= sc; }
            mx0 = tm0;
        }
        if (tm1 > mx1) {
            float sc = __expf(mx1 - tm1);
            l1 *= sc;
            #pragma unroll
            for (int nt = 0; nt < 8; nt++) { O[nt][2] *= sc; O[nt][3] *= sc; }
            mx1 = tm1;
        }

        uint32_t P0[8], P1[8];
        #pragma unroll
        for (int nt = 0; nt < 8; nt++) {
            float p0 = __expf(S[nt][0] - mx0);
            float p1 = __expf(S[nt][1] - mx0);
            float p2 = __expf(S[nt][2] - mx1);
            float p3 = __expf(S[nt][3] - mx1);
            uint32_t a = pack_bf16(p0, p1);
            uint32_t b = pack_bf16(p2, p3);
            P0[nt] = a; P1[nt] = b;
            l0 += bf2sum(a);           // l from ROUNDED p (consistency)
            l1 += bf2sum(b);
        }

        // ---- O += P V (V split hi/lo) ----
        #pragma unroll
        for (int ks2 = 0; ks2 < 4; ks2++) {
            uint32_t af[4] = {P0[2 * ks2], P1[2 * ks2],
                              P0[2 * ks2 + 1], P1[2 * ks2 + 1]};
            #pragma unroll
            for (int np = 0; np < 4; np++) {
                uint32_t vh[4], vl[4];
                uint32_t off = (uint32_t)(voff + ks2 * 16 * VS + np * 16) * 2;
                ldm_x4t(vh, svh + off);
                ldm_x4t(vl, svl + off);
                mma_bf16(O[2 * np],     af, &vh[0]);
                mma_bf16(O[2 * np],     af, &vl[0]);
                mma_bf16(O[2 * np + 1], af, &vh[2]);
                mma_bf16(O[2 * np + 1], af, &vl[2]);
            }
        }
        __syncthreads();
    }

    l0 += __shfl_xor_sync(0xffffffffu, l0, 1);
    l0 += __shfl_xor_sync(0xffffffffu, l0, 2);
    l1 += __shfl_xor_sync(0xffffffffu, l1, 1);
    l1 += __shfl_xor_sync(0xffffffffu, l1, 2);
    float i0 = 1.f / l0, i1 = 1.f / l1;

    #pragma unroll
    for (int nt = 0; nt < 8; nt++) {
        int nn = h * DK + nt * 8 + (lane & 3) * 2;
        *(float2*)(out + (size_t)r0 * DM + nn) =
            make_float2(O[nt][0] * i0, O[nt][1] * i0);
        *(float2*)(out + (size_t)(r0 + 8) * DM + nn) =
            make_float2(O[nt][2] * i1, O[nt][3] * i1);
    }
}

// ---------------------------------------------------------------------------
extern "C" void kernel_launch(void* const* d_in, const int* in_sizes, int n_in,
                              void* d_out, int out_size)
{
    const float* query = (const float*)d_in[0];
    const float* key   = (const float*)d_in[1];
    const float* value = (const float*)d_in[2];
    const float* bemb  = (const float*)d_in[3];
    const unsigned int* mask = (const unsigned int*)d_in[4];
    const float* LL    = (const float*)d_in[5];
    const float* bproj = (const float*)d_in[6];
    float* out = (float*)d_out;

    static int smem_set = 0;
    if (!smem_set) {
        cudaFuncSetAttribute(attn_mma,
                             cudaFuncAttributeMaxDynamicSharedMemorySize,
                             120 * 1024);
        smem_set = 1;
    }
    const int ATTN_SMEM = (2 * 256 * VS + 4 * 64 * VS) * 2 + SEQ;

    conv_x<<<4 * SEQ * DM / 4 / 256, 256>>>(query, key, value, bemb);
    conv_w<<<dim3(DM / 32, DM / 32, 4), 256>>>(LL, bproj);

    proj_mma<<<dim3(DM / 128, SEQ / 128, 4), 256>>>();

    rope_split<<<(SEQ * NH * 32) / 256, 256>>>();

    attn_mma<<<dim3(SEQ / 256, NH), 512, ATTN_SMEM>>>(mask, out);
}

// round 9
// speedup vs baseline: 4.1079x; 1.1105x over previous
#include <cuda_runtime.h>
#include <cuda_bf16.h>
#include <math.h>
#include <stdint.h>

#define SEQ 2048
#define DM 1024
#define NH 16
#define DK 64

// fp32 intermediate (b_rotate projection)
__device__ float g_BR[SEQ * DM];

// split-bf16 proj inputs [4][SEQ][DM] (q,k,v,b_emb), weights transposed [4][n][k]
__device__ __nv_bfloat16 g_Xhi[4 * SEQ * DM];
__device__ __nv_bfloat16 g_Xlo[4 * SEQ * DM];
__device__ __nv_bfloat16 g_Whi[4 * DM * DM];
__device__ __nv_bfloat16 g_Wlo[4 * DM * DM];
// attention operands (written by proj epilogue, rope fused)
__device__ __nv_bfloat16 g_Qhi[SEQ * DM];
__device__ __nv_bfloat16 g_Qlo[SEQ * DM];
__device__ __nv_bfloat16 g_Khi[SEQ * DM];
__device__ __nv_bfloat16 g_Klo[SEQ * DM];
__device__ __nv_bfloat16 g_Vhi[SEQ * DM];
__device__ __nv_bfloat16 g_Vlo[SEQ * DM];

__device__ __forceinline__ uint32_t smem_u32(const void* p) {
    uint32_t a;
    asm("{ .reg .u64 t; cvta.to.shared.u64 t, %1; cvt.u32.u64 %0, t; }"
        : "=r"(a) : "l"(p));
    return a;
}
__device__ __forceinline__ void ldm_x4(uint32_t r[4], uint32_t addr) {
    asm volatile("ldmatrix.sync.aligned.m8n8.x4.shared.b16 {%0,%1,%2,%3}, [%4];"
                 : "=r"(r[0]), "=r"(r[1]), "=r"(r[2]), "=r"(r[3]) : "r"(addr));
}
__device__ __forceinline__ void ldm_x4t(uint32_t r[4], uint32_t addr) {
    asm volatile("ldmatrix.sync.aligned.m8n8.x4.trans.shared.b16 {%0,%1,%2,%3}, [%4];"
                 : "=r"(r[0]), "=r"(r[1]), "=r"(r[2]), "=r"(r[3]) : "r"(addr));
}
__device__ __forceinline__ void mma_bf16(float c[4], const uint32_t a[4],
                                         const uint32_t* b) {
    asm volatile(
        "mma.sync.aligned.m16n8k16.row.col.f32.bf16.bf16.f32 "
        "{%0,%1,%2,%3}, {%4,%5,%6,%7}, {%8,%9}, {%0,%1,%2,%3};"
        : "+f"(c[0]), "+f"(c[1]), "+f"(c[2]), "+f"(c[3])
        : "r"(a[0]), "r"(a[1]), "r"(a[2]), "r"(a[3]), "r"(b[0]), "r"(b[1]));
}
__device__ __forceinline__ uint32_t pack_bf16(float a, float b) {
    __nv_bfloat162 t = __floats2bfloat162_rn(a, b);
    return *(uint32_t*)&t;
}
__device__ __forceinline__ float bf2sum(uint32_t p) {
    __nv_bfloat162 b = *(__nv_bfloat162*)&p;
    return __bfloat162float(b.x) + __bfloat162float(b.y);
}

// ---------------------------------------------------------------------------
// conv_x: fp32 inputs -> hi/lo bf16 [4][SEQ][DM]
// ---------------------------------------------------------------------------
__global__ __launch_bounds__(256) void conv_x(
    const float* __restrict__ q, const float* __restrict__ k,
    const float* __restrict__ v, const float* __restrict__ b)
{
    const int PER = SEQ * DM / 4;
    int t = blockIdx.x * 256 + threadIdx.x;
    int z = t / PER, i = t - z * PER;
    const float* src = (z == 0) ? q : (z == 1) ? k : (z == 2) ? v : b;
    float4 x = ((const float4*)src)[i];

    __nv_bfloat16 h0 = __float2bfloat16(x.x), h1 = __float2bfloat16(x.y);
    __nv_bfloat16 h2 = __float2bfloat16(x.z), h3 = __float2bfloat16(x.w);
    __nv_bfloat162 hA = {h0, h1}, hB = {h2, h3};
    __nv_bfloat162 lA = {__float2bfloat16(x.x - __bfloat162float(h0)),
                         __float2bfloat16(x.y - __bfloat162float(h1))};
    __nv_bfloat162 lB = {__float2bfloat16(x.z - __bfloat162float(h2)),
                         __float2bfloat16(x.w - __bfloat162float(h3))};
    size_t o = (size_t)z * SEQ * DM + (size_t)i * 4;
    *(uint2*)(g_Xhi + o) = make_uint2(*(uint32_t*)&hA, *(uint32_t*)&hB);
    *(uint2*)(g_Xlo + o) = make_uint2(*(uint32_t*)&lA, *(uint32_t*)&lB);
}

// ---------------------------------------------------------------------------
// conv_w: fp32 weights W[k][n] -> transposed hi/lo bf16 WT[n][k]
// ---------------------------------------------------------------------------
__global__ __launch_bounds__(256) void conv_w(
    const float* __restrict__ LL, const float* __restrict__ bproj)
{
    int z = blockIdx.z;
    const float* W = (z < 3) ? (LL + (size_t)z * DM * DM) : bproj;
    int k0 = blockIdx.y * 32, n0 = blockIdx.x * 32;

    __shared__ float tile[32][33];
    int tid = threadIdx.x;
    #pragma unroll
    for (int i = 0; i < 4; i++) {
        int f = tid + i * 256, r = f >> 5, c = f & 31;
        tile[r][c] = W[(size_t)(k0 + r) * DM + n0 + c];
    }
    __syncthreads();
    #pragma unroll
    for (int i = 0; i < 4; i++) {
        int f = tid + i * 256, r = f >> 5, c = f & 31;
        float x = tile[c][r];
        __nv_bfloat16 h = __float2bfloat16(x);
        size_t o = (size_t)z * DM * DM + (size_t)(n0 + r) * DM + k0 + c;
        g_Whi[o] = h;
        g_Wlo[o] = __float2bfloat16(x - __bfloat162float(h));
    }
}

// ---------------------------------------------------------------------------
// proj_mma: C = X @ W, split-bf16, 3 cross-products (hi*hi, hi*lo, lo*hi).
// zbase=3: b_rotate -> g_BR fp32.
// zbase=0 (z=0,1,2): fused rope+b_rotate epilogue -> split bf16 Q/K; V split.
// ---------------------------------------------------------------------------
#define SAS 40

__global__ __launch_bounds__(256) void proj_mma(int zbase)
{
    __shared__ __nv_bfloat16 sAh[128 * SAS], sAl[128 * SAS];
    __shared__ __nv_bfloat16 sBh[128 * SAS], sBl[128 * SAS];

    int z = zbase + blockIdx.z;
    int m0 = blockIdx.y * 128, n0 = blockIdx.x * 128;
    const __nv_bfloat16* Ah = g_Xhi + (size_t)z * SEQ * DM;
    const __nv_bfloat16* Al = g_Xlo + (size_t)z * SEQ * DM;
    const __nv_bfloat16* Bh = g_Whi + (size_t)z * DM * DM;
    const __nv_bfloat16* Bl = g_Wlo + (size_t)z * DM * DM;

    int tid = threadIdx.x, lane = tid & 31, wid = tid >> 5;
    int wm = wid & 3, wn = wid >> 2;

    int lrow[8], lcol[8];
    #pragma unroll
    for (int i = 0; i < 8; i++) { int f = i * 256 + tid; lrow[i] = f >> 4; lcol[i] = (f & 15) * 2; }

    uint32_t pAh[8], pAl[8], pBh[8], pBl[8];
    #pragma unroll
    for (int i = 0; i < 8; i++) {
        size_t oa = (size_t)(m0 + lrow[i]) * DM + lcol[i];
        size_t ob = (size_t)(n0 + lrow[i]) * DM + lcol[i];
        pAh[i] = *(const uint32_t*)(Ah + oa);
        pAl[i] = *(const uint32_t*)(Al + oa);
        pBh[i] = *(const uint32_t*)(Bh + ob);
        pBl[i] = *(const uint32_t*)(Bl + ob);
    }

    float acc[2][8][4];
    #pragma unroll
    for (int mt = 0; mt < 2; mt++)
        #pragma unroll
        for (int nt = 0; nt < 8; nt++)
            #pragma unroll
            for (int e = 0; e < 4; e++) acc[mt][nt][e] = 0.f;

    uint32_t sa_h = smem_u32(sAh), sa_l = smem_u32(sAl);
    uint32_t sb_h = smem_u32(sBh), sb_l = smem_u32(sBl);
    int aoff = (wm * 32 + (lane & 15)) * SAS + (lane >> 4) * 8;
    int boff = (wn * 64 + ((lane >> 4) & 1) * 8 + (lane & 7)) * SAS + ((lane >> 3) & 1) * 8;

    const int NCH = DM / 32;
    for (int c = 0; c < NCH; c++) {
        #pragma unroll
        for (int i = 0; i < 8; i++) {
            int so = lrow[i] * SAS + lcol[i];
            *(uint32_t*)(sAh + so) = pAh[i];
            *(uint32_t*)(sAl + so) = pAl[i];
            *(uint32_t*)(sBh + so) = pBh[i];
            *(uint32_t*)(sBl + so) = pBl[i];
        }
        __syncthreads();

        if (c + 1 < NCH) {
            int k0 = (c + 1) * 32;
            #pragma unroll
            for (int i = 0; i < 8; i++) {
                size_t oa = (size_t)(m0 + lrow[i]) * DM + k0 + lcol[i];
                size_t ob = (size_t)(n0 + lrow[i]) * DM + k0 + lcol[i];
                pAh[i] = *(const uint32_t*)(Ah + oa);
                pAl[i] = *(const uint32_t*)(Al + oa);
                pBh[i] = *(const uint32_t*)(Bh + ob);
                pBl[i] = *(const uint32_t*)(Bl + ob);
            }
        }

        #pragma unroll
        for (int ks = 0; ks < 2; ks++) {
            uint32_t ah[2][4], al[2][4];
            #pragma unroll
            for (int mt = 0; mt < 2; mt++) {
                uint32_t off = (uint32_t)(aoff + mt * 16 * SAS + ks * 16) * 2;
                ldm_x4(ah[mt], sa_h + off);
                ldm_x4(al[mt], sa_l + off);
            }
            uint32_t bh[4][4], bl[4][4];
            #pragma unroll
            for (int np = 0; np < 4; np++) {
                uint32_t off = (uint32_t)(boff + np * 16 * SAS + ks * 16) * 2;
                ldm_x4(bh[np], sb_h + off);
                ldm_x4(bl[np], sb_l + off);
            }
            #pragma unroll
            for (int mt = 0; mt < 2; mt++)
                #pragma unroll
                for (int nt = 0; nt < 8; nt++) {
                    const uint32_t* Bhf = &bh[nt >> 1][(nt & 1) * 2];
                    const uint32_t* Blf = &bl[nt >> 1][(nt & 1) * 2];
                    mma_bf16(acc[mt][nt], ah[mt], Bhf);
                    mma_bf16(acc[mt][nt], ah[mt], Blf);
                    mma_bf16(acc[mt][nt], al[mt], Bhf);
                }
        }
        __syncthreads();
    }

    int mbase = m0 + wm * 32 + (lane >> 2);
    int nbase = n0 + wn * 64 + (lane & 3) * 2;

    if (z == 3) {
        // b_rotate: fp32 out
        #pragma unroll
        for (int mt = 0; mt < 2; mt++)
            #pragma unroll
            for (int nt = 0; nt < 8; nt++) {
                int mm = mbase + mt * 16, nn = nbase + nt * 8;
                *(float2*)(g_BR + (size_t)mm * DM + nn) =
                    make_float2(acc[mt][nt][0], acc[mt][nt][1]);
                *(float2*)(g_BR + (size_t)(mm + 8) * DM + nn) =
                    make_float2(acc[mt][nt][2], acc[mt][nt][3]);
            }
    } else if (z == 2) {
        // V: split-bf16
        #pragma unroll
        for (int mt = 0; mt < 2; mt++)
            #pragma unroll
            for (int nt = 0; nt < 8; nt++) {
                int mm = mbase + mt * 16, nn = nbase + nt * 8;
                #pragma unroll
                for (int half = 0; half < 2; half++) {
                    float x = acc[mt][nt][half * 2], y = acc[mt][nt][half * 2 + 1];
                    float hx = __bfloat162float(__float2bfloat16(x));
                    float hy = __bfloat162float(__float2bfloat16(y));
                    size_t o = (size_t)(mm + half * 8) * DM + nn;
                    *(uint32_t*)(g_Vhi + o) = pack_bf16(x, y);
                    *(uint32_t*)(g_Vlo + o) = pack_bf16(x - hx, y - hy);
                }
            }
    } else {
        // Q (z=0) / K (z=1): fused rope + b_rotate, split-bf16 out
        __nv_bfloat16* Dhi = (z == 0) ? g_Qhi : g_Khi;
        __nv_bfloat16* Dlo = (z == 0) ? g_Qlo : g_Klo;
        float qscale = (z == 0) ? 0.125f : 1.0f;
        #pragma unroll
        for (int nt = 0; nt < 8; nt++) {
            int nn = nbase + nt * 8;
            int i = (nn & 63) >> 1;   // rope pair index within head
            float inv = (float)exp(-(double)i * (9.210340371976184 / 32.0));
            #pragma unroll
            for (int mt = 0; mt < 2; mt++) {
                #pragma unroll
                for (int half = 0; half < 2; half++) {
                    int mm = mbase + mt * 16 + half * 8;
                    float x1 = acc[mt][nt][half * 2];
                    float x2 = acc[mt][nt][half * 2 + 1];
                    float sa, ca;
                    sincosf((float)mm * inv, &sa, &ca);
                    size_t o = (size_t)mm * DM + nn;
                    float2 br = *(const float2*)(g_BR + o);
                    float e  = (x1 * ca - x2 * sa) * br.x * qscale;
                    float od = (x1 * sa + x2 * ca) * br.y * qscale;
                    float eh = __bfloat162float(__float2bfloat16(e));
                    float oh = __bfloat162float(__float2bfloat16(od));
                    *(uint32_t*)(Dhi + o) = pack_bf16(e, od);
                    *(uint32_t*)(Dlo + o) = pack_bf16(e - eh, od - oh);
                }
            }
        }
    }
}

// ---------------------------------------------------------------------------
// attn_mma: flash attention on mma.sync.
// Grid (SEQ/256, NH), 512 thr / 16 warps, 16 q-rows per warp, BN=64.
// S: Q,K split (3 products). PV: P bf16 (l summed from rounded p), V split.
// K/V global loads register-prefetched one tile ahead.
// ---------------------------------------------------------------------------
#define VS 72   // smem row stride (elems) for 64-wide tiles

__global__ __launch_bounds__(512) void attn_mma(
    const unsigned int* __restrict__ mask, float* __restrict__ out)
{
    extern __shared__ __align__(16) char dyn[];
    __nv_bfloat16* sQh = (__nv_bfloat16*)dyn;            // 256 x VS
    __nv_bfloat16* sQl = sQh + 256 * VS;
    __nv_bfloat16* sKh = sQl + 256 * VS;                 // 64 x VS
    __nv_bfloat16* sKl = sKh + 64 * VS;
    __nv_bfloat16* sVh = sKl + 64 * VS;
    __nv_bfloat16* sVl = sVh + 64 * VS;
    unsigned char* smk = (unsigned char*)(sVl + 64 * VS);

    int h = blockIdx.y, m0 = blockIdx.x * 256;
    int tid = threadIdx.x, lane = tid & 31, wid = tid >> 5;

    for (int i = tid; i < SEQ; i += 512)
        smk[i] = (mask[i] != 0u) ? 1 : 0;

    // stage Q hi/lo: 256 rows x 16 uint2 per array
    #pragma unroll
    for (int i = 0; i < 8; i++) {
        int f = tid + i * 512, row = f >> 4, c4 = f & 15;
        size_t g = (size_t)(m0 + row) * DM + h * DK + c4 * 4;
        *(uint2*)(sQh + row * VS + c4 * 4) = *(const uint2*)(g_Qhi + g);
        *(uint2*)(sQl + row * VS + c4 * 4) = *(const uint2*)(g_Qlo + g);
    }

    int r0 = m0 + wid * 16 + (lane >> 2);
    bool mr0 = (mask[r0] != 0u), mr1 = (mask[r0 + 8] != 0u);

    float mx0 = -INFINITY, mx1 = -INFINITY, l0 = 0.f, l1 = 0.f;
    float O[8][4];
    #pragma unroll
    for (int nt = 0; nt < 8; nt++)
        #pragma unroll
        for (int e = 0; e < 4; e++) O[nt][e] = 0.f;

    uint32_t sqh = smem_u32(sQh), sql = smem_u32(sQl);
    uint32_t skh = smem_u32(sKh), skl = smem_u32(sKl);
    uint32_t svh = smem_u32(sVh), svl = smem_u32(sVl);

    int qoff = (wid * 16 + (lane & 15)) * VS + (lane >> 4) * 8;
    int kboff = ((lane & 7) + ((lane >> 4) & 1) * 8) * VS + ((lane >> 3) & 1) * 8;
    int voff = (lane & 15) * VS + ((lane >> 4) & 1) * 8;

    // prefetch K/V tile 0 (2 uint2 per thread per array)
    int prow[2], pc4[2];
    #pragma unroll
    for (int i = 0; i < 2; i++) { int f = tid + i * 512; prow[i] = f >> 4; pc4[i] = f & 15; }
    uint2 pkh[2], pkl[2], pvh[2], pvl[2];
    #pragma unroll
    for (int i = 0; i < 2; i++) {
        size_t g = (size_t)prow[i] * DM + h * DK + pc4[i] * 4;
        pkh[i] = *(const uint2*)(g_Khi + g);
        pkl[i] = *(const uint2*)(g_Klo + g);
        pvh[i] = *(const uint2*)(g_Vhi + g);
        pvl[i] = *(const uint2*)(g_Vlo + g);
    }

    for (int kb = 0; kb < SEQ / 64; kb++) {
        // store prefetched tile
        #pragma unroll
        for (int i = 0; i < 2; i++) {
            int so = prow[i] * VS + pc4[i] * 4;
            *(uint2*)(sKh + so) = pkh[i];
            *(uint2*)(sKl + so) = pkl[i];
            *(uint2*)(sVh + so) = pvh[i];
            *(uint2*)(sVl + so) = pvl[i];
        }
        __syncthreads();

        // prefetch next tile (latency hidden by compute below)
        if (kb + 1 < SEQ / 64) {
            #pragma unroll
            for (int i = 0; i < 2; i++) {
                size_t g = (size_t)((kb + 1) * 64 + prow[i]) * DM + h * DK + pc4[i] * 4;
                pkh[i] = *(const uint2*)(g_Khi + g);
                pkl[i] = *(const uint2*)(g_Klo + g);
                pvh[i] = *(const uint2*)(g_Vhi + g);
                pvl[i] = *(const uint2*)(g_Vlo + g);
            }
        }

        // ---- S = Q K^T (3 products) ----
        float S[8][4];
        #pragma unroll
        for (int nt = 0; nt < 8; nt++)
            #pragma unroll
            for (int e = 0; e < 4; e++) S[nt][e] = 0.f;

        #pragma unroll
        for (int ks = 0; ks < 4; ks++) {
            uint32_t qh[4], ql[4];
            ldm_x4(qh, sqh + (uint32_t)(qoff + ks * 16) * 2);
            ldm_x4(ql, sql + (uint32_t)(qoff + ks * 16) * 2);
            #pragma unroll
            for (int np = 0; np < 4; np++) {
                uint32_t bh[4], bl[4];
                uint32_t off = (uint32_t)(kboff + np * 16 * VS + ks * 16) * 2;
                ldm_x4(bh, skh + off);
                ldm_x4(bl, skl + off);
                mma_bf16(S[2 * np],     qh, &bh[0]);
                mma_bf16(S[2 * np],     qh, &bl[0]);
                mma_bf16(S[2 * np],     ql, &bh[0]);
                mma_bf16(S[2 * np + 1], qh, &bh[2]);
                mma_bf16(S[2 * np + 1], qh, &bl[2]);
                mma_bf16(S[2 * np + 1], ql, &bh[2]);
            }
        }

        // ---- mask + online softmax ----
        float tm0 = -INFINITY, tm1 = -INFINITY;
        #pragma unroll
        for (int nt = 0; nt < 8; nt++) {
            int col = kb * 64 + nt * 8 + (lane & 3) * 2;
            bool c0 = smk[col] != 0, c1 = smk[col + 1] != 0;
            S[nt][0] = (mr0 && c0) ? S[nt][0] : -1e30f;
            S[nt][1] = (mr0 && c1) ? S[nt][1] : -1e30f;
            S[nt][2] = (mr1 && c0) ? S[nt][2] : -1e30f;
            S[nt][3] = (mr1 && c1) ? S[nt][3] : -1e30f;
            tm0 = fmaxf(tm0, fmaxf(S[nt][0], S[nt][1]));
            tm1 = fmaxf(tm1, fmaxf(S[nt][2], S[nt][3]));
        }
        tm0 = fmaxf(tm0, __shfl_xor_sync(0xffffffffu, tm0, 1));
        tm0 = fmaxf(tm0, __shfl_xor_sync(0xffffffffu, tm0, 2));
        tm1 = fmaxf(tm1, __shfl_xor_sync(0xffffffffu, tm1, 1));
        tm1 = fmaxf(tm1, __shfl_xor_sync(0xffffffffu, tm1, 2));

        if (tm0 > mx0) {
            float sc = __expf(mx0 - tm0);
            l0 *= sc;
            #pragma unroll
            for (int nt = 0; nt < 8; nt++) { O[nt][0] *= sc; O[nt][1] *= sc; }
            mx0 = tm0;
        }
        if (tm1 > mx1) {
            float sc = __expf(mx1 - tm1);
            l1 *= sc;
            #pragma unroll
            for (int nt = 0; nt < 8; nt++) { O[nt][2] *= sc; O[nt][3] *= sc; }
            mx1 = tm1;
        }

        uint32_t P0[8], P1[8];
        #pragma unroll
        for (int nt = 0; nt < 8; nt++) {
            float p0 = __expf(S[nt][0] - mx0);
            float p1 = __expf(S[nt][1] - mx0);
            float p2 = __expf(S[nt][2] - mx1);
            float p3 = __expf(S[nt][3] - mx1);
            uint32_t a = pack_bf16(p0, p1);
            uint32_t b = pack_bf16(p2, p3);
            P0[nt] = a; P1[nt] = b;
            l0 += bf2sum(a);           // l from ROUNDED p (consistency)
            l1 += bf2sum(b);
        }

        // ---- O += P V (V split hi/lo) ----
        #pragma unroll
        for (int ks2 = 0; ks2 < 4; ks2++) {
            uint32_t af[4] = {P0[2 * ks2], P1[2 * ks2],
                              P0[2 * ks2 + 1], P1[2 * ks2 + 1]};
            #pragma unroll
            for (int np = 0; np < 4; np++) {
                uint32_t vh[4], vl[4];
                uint32_t off = (uint32_t)(voff + ks2 * 16 * VS + np * 16) * 2;
                ldm_x4t(vh, svh + off);
                ldm_x4t(vl, svl + off);
                mma_bf16(O[2 * np],     af, &vh[0]);
                mma_bf16(O[2 * np],     af, &vl[0]);
                mma_bf16(O[2 * np + 1], af, &vh[2]);
                mma_bf16(O[2 * np + 1], af, &vl[2]);
            }
        }
        __syncthreads();
    }

    l0 += __shfl_xor_sync(0xffffffffu, l0, 1);
    l0 += __shfl_xor_sync(0xffffffffu, l0, 2);
    l1 += __shfl_xor_sync(0xffffffffu, l1, 1);
    l1 += __shfl_xor_sync(0xffffffffu, l1, 2);
    float i0 = 1.f / l0, i1 = 1.f / l1;

    #pragma unroll
    for (int nt = 0; nt < 8; nt++) {
        int nn = h * DK + nt * 8 + (lane & 3) * 2;
        *(float2*)(out + (size_t)r0 * DM + nn) =
            make_float2(O[nt][0] * i0, O[nt][1] * i0);
        *(float2*)(out + (size_t)(r0 + 8) * DM + nn) =
            make_float2(O[nt][2] * i1, O[nt][3] * i1);
    }
}

// ---------------------------------------------------------------------------
extern "C" void kernel_launch(void* const* d_in, const int* in_sizes, int n_in,
                              void* d_out, int out_size)
{
    const float* query = (const float*)d_in[0];
    const float* key   = (const float*)d_in[1];
    const float* value = (const float*)d_in[2];
    const float* bemb  = (const float*)d_in[3];
    const unsigned int* mask = (const unsigned int*)d_in[4];
    const float* LL    = (const float*)d_in[5];
    const float* bproj = (const float*)d_in[6];
    float* out = (float*)d_out;

    static int smem_set = 0;
    if (!smem_set) {
        cudaFuncSetAttribute(attn_mma,
                             cudaFuncAttributeMaxDynamicSharedMemorySize,
                             120 * 1024);
        smem_set = 1;
    }
    const int ATTN_SMEM = (2 * 256 * VS + 4 * 64 * VS) * 2 + SEQ;

    conv_x<<<4 * SEQ * DM / 4 / 256, 256>>>(query, key, value, bemb);
    conv_w<<<dim3(DM / 32, DM / 32, 4), 256>>>(LL, bproj);

    proj_mma<<<dim3(DM / 128, SEQ / 128, 1), 256>>>(3);   // b_rotate first
    proj_mma<<<dim3(DM / 128, SEQ / 128, 3), 256>>>(0);   // Q,K,V + fused rope

    attn_mma<<<dim3(SEQ / 256, NH), 512, ATTN_SMEM>>>(mask, out);
}

// round 10
// speedup vs baseline: 4.6027x; 1.1204x over previous
#include <cuda_runtime.h>
#include <cuda_bf16.h>
#include <math.h>
#include <stdint.h>

#define SEQ 2048
#define DM 1024
#define NH 16
#define DK 64

// fp32 intermediate (b_rotate projection)
__device__ float g_BR[SEQ * DM];

// split-bf16 proj inputs [4][SEQ][DM] (q,k,v,b_emb), weights transposed [4][n][k]
__device__ __nv_bfloat16 g_Xhi[4 * SEQ * DM];
__device__ __nv_bfloat16 g_Xlo[4 * SEQ * DM];
__device__ __nv_bfloat16 g_Whi[4 * DM * DM];
__device__ __nv_bfloat16 g_Wlo[4 * DM * DM];
// attention operands (written by proj epilogue, rope fused)
__device__ __nv_bfloat16 g_Qhi[SEQ * DM];
__device__ __nv_bfloat16 g_Qlo[SEQ * DM];
__device__ __nv_bfloat16 g_Khi[SEQ * DM];
__device__ __nv_bfloat16 g_Klo[SEQ * DM];
__device__ __nv_bfloat16 g_Vhi[SEQ * DM];
__device__ __nv_bfloat16 g_Vlo[SEQ * DM];

__device__ __forceinline__ uint32_t smem_u32(const void* p) {
    uint32_t a;
    asm("{ .reg .u64 t; cvta.to.shared.u64 t, %1; cvt.u32.u64 %0, t; }"
        : "=r"(a) : "l"(p));
    return a;
}
__device__ __forceinline__ void ldm_x4(uint32_t r[4], uint32_t addr) {
    asm volatile("ldmatrix.sync.aligned.m8n8.x4.shared.b16 {%0,%1,%2,%3}, [%4];"
                 : "=r"(r[0]), "=r"(r[1]), "=r"(r[2]), "=r"(r[3]) : "r"(addr));
}
__device__ __forceinline__ void ldm_x4t(uint32_t r[4], uint32_t addr) {
    asm volatile("ldmatrix.sync.aligned.m8n8.x4.trans.shared.b16 {%0,%1,%2,%3}, [%4];"
                 : "=r"(r[0]), "=r"(r[1]), "=r"(r[2]), "=r"(r[3]) : "r"(addr));
}
__device__ __forceinline__ void mma_bf16(float c[4], const uint32_t a[4],
                                         const uint32_t* b) {
    asm volatile(
        "mma.sync.aligned.m16n8k16.row.col.f32.bf16.bf16.f32 "
        "{%0,%1,%2,%3}, {%4,%5,%6,%7}, {%8,%9}, {%0,%1,%2,%3};"
        : "+f"(c[0]), "+f"(c[1]), "+f"(c[2]), "+f"(c[3])
        : "r"(a[0]), "r"(a[1]), "r"(a[2]), "r"(a[3]), "r"(b[0]), "r"(b[1]));
}
__device__ __forceinline__ uint32_t pack_bf16(float a, float b) {
    __nv_bfloat162 t = __floats2bfloat162_rn(a, b);
    return *(uint32_t*)&t;
}
__device__ __forceinline__ float bf2sum(uint32_t p) {
    __nv_bfloat162 b = *(__nv_bfloat162*)&p;
    return __bfloat162float(b.x) + __bfloat162float(b.y);
}
#define CP16(s, g) \
    asm volatile("cp.async.cg.shared.global [%0], [%1], 16;" \
                 :: "r"(s), "l"(g) : "memory")
#define CP_COMMIT() asm volatile("cp.async.commit_group;" ::: "memory")
#define CP_WAIT2()  asm volatile("cp.async.wait_group 2;" ::: "memory")

// ---------------------------------------------------------------------------
// conv_x: fp32 inputs -> hi/lo bf16 [4][SEQ][DM]
// ---------------------------------------------------------------------------
__global__ __launch_bounds__(256) void conv_x(
    const float* __restrict__ q, const float* __restrict__ k,
    const float* __restrict__ v, const float* __restrict__ b)
{
    const int PER = SEQ * DM / 4;
    int t = blockIdx.x * 256 + threadIdx.x;
    int z = t / PER, i = t - z * PER;
    const float* src = (z == 0) ? q : (z == 1) ? k : (z == 2) ? v : b;
    float4 x = ((const float4*)src)[i];

    __nv_bfloat16 h0 = __float2bfloat16(x.x), h1 = __float2bfloat16(x.y);
    __nv_bfloat16 h2 = __float2bfloat16(x.z), h3 = __float2bfloat16(x.w);
    __nv_bfloat162 hA = {h0, h1}, hB = {h2, h3};
    __nv_bfloat162 lA = {__float2bfloat16(x.x - __bfloat162float(h0)),
                         __float2bfloat16(x.y - __bfloat162float(h1))};
    __nv_bfloat162 lB = {__float2bfloat16(x.z - __bfloat162float(h2)),
                         __float2bfloat16(x.w - __bfloat162float(h3))};
    size_t o = (size_t)z * SEQ * DM + (size_t)i * 4;
    *(uint2*)(g_Xhi + o) = make_uint2(*(uint32_t*)&hA, *(uint32_t*)&hB);
    *(uint2*)(g_Xlo + o) = make_uint2(*(uint32_t*)&lA, *(uint32_t*)&lB);
}

// ---------------------------------------------------------------------------
// conv_w: fp32 weights W[k][n] -> transposed hi/lo bf16 WT[n][k]
// ---------------------------------------------------------------------------
__global__ __launch_bounds__(256) void conv_w(
    const float* __restrict__ LL, const float* __restrict__ bproj)
{
    int z = blockIdx.z;
    const float* W = (z < 3) ? (LL + (size_t)z * DM * DM) : bproj;
    int k0 = blockIdx.y * 32, n0 = blockIdx.x * 32;

    __shared__ float tile[32][33];
    int tid = threadIdx.x;
    #pragma unroll
    for (int i = 0; i < 4; i++) {
        int f = tid + i * 256, r = f >> 5, c = f & 31;
        tile[r][c] = W[(size_t)(k0 + r) * DM + n0 + c];
    }
    __syncthreads();
    #pragma unroll
    for (int i = 0; i < 4; i++) {
        int f = tid + i * 256, r = f >> 5, c = f & 31;
        float x = tile[c][r];
        __nv_bfloat16 h = __float2bfloat16(x);
        size_t o = (size_t)z * DM * DM + (size_t)(n0 + r) * DM + k0 + c;
        g_Whi[o] = h;
        g_Wlo[o] = __float2bfloat16(x - __bfloat162float(h));
    }
}

// ---------------------------------------------------------------------------
// proj_mma: C = X @ W, split-bf16, 3 cross-products.
// BM=128, BN=64, BK=32, 256 thr, 8 warps (4m x 2n), warp tile 32x32.
// cp.async 3-stage smem ring, 2 CTAs/SM.
// zbase=3: b_rotate -> g_BR fp32.  zbase=0: Q/K fused-rope split, V split.
// ---------------------------------------------------------------------------
#define SAS 40
#define STG 3
#define A_ST (128 * SAS)          // elems per A array (hi or lo)
#define B_ST (64 * SAS)
#define STAGE_EL (2 * A_ST + 2 * B_ST)
#define PROJ_SMEM (STG * STAGE_EL * 2)

__global__ __launch_bounds__(256, 2) void proj_mma(int zbase)
{
    extern __shared__ __align__(16) __nv_bfloat16 dsm[];

    int z = zbase + blockIdx.z;
    int m0 = blockIdx.y * 128, n0 = blockIdx.x * 64;
    const __nv_bfloat16* Ah = g_Xhi + (size_t)z * SEQ * DM;
    const __nv_bfloat16* Al = g_Xlo + (size_t)z * SEQ * DM;
    const __nv_bfloat16* Bh = g_Whi + (size_t)z * DM * DM;
    const __nv_bfloat16* Bl = g_Wlo + (size_t)z * DM * DM;

    int tid = threadIdx.x, lane = tid & 31, wid = tid >> 5;
    int wm = wid & 3, wn = wid >> 2;

    uint32_t sbase = smem_u32(dsm);

    // A: 512 16B-chunks (128 rows x 4), 2 per thread; B: 256 chunks, 1 per thread
    int ar0 = tid >> 2,         ac0 = tid & 3;
    int ar1 = (tid + 256) >> 2, ac1 = (tid + 256) & 3;
    int br = tid >> 2,          bc = tid & 3;

    const int NCH = DM / 32;

    // issue loads for chunk c into stage s
    auto issue = [&](int s, int c) {
        uint32_t st = sbase + (uint32_t)s * STAGE_EL * 2;
        int k0 = c * 32;
        uint32_t sa0 = st + (uint32_t)(ar0 * SAS + ac0 * 8) * 2;
        uint32_t sa1 = st + (uint32_t)(ar1 * SAS + ac1 * 8) * 2;
        size_t ga0 = (size_t)(m0 + ar0) * DM + k0 + ac0 * 8;
        size_t ga1 = (size_t)(m0 + ar1) * DM + k0 + ac1 * 8;
        CP16(sa0, Ah + ga0);
        CP16(sa0 + A_ST * 2, Al + ga0);
        CP16(sa1, Ah + ga1);
        CP16(sa1 + A_ST * 2, Al + ga1);
        uint32_t sb = st + (uint32_t)(2 * A_ST + br * SAS + bc * 8) * 2;
        size_t gb = (size_t)(n0 + br) * DM + k0 + bc * 8;
        CP16(sb, Bh + gb);
        CP16(sb + B_ST * 2, Bl + gb);
    };

    #pragma unroll
    for (int s = 0; s < STG; s++) { issue(s, s); CP_COMMIT(); }

    float acc[2][4][4];
    #pragma unroll
    for (int mt = 0; mt < 2; mt++)
        #pragma unroll
        for (int nt = 0; nt < 4; nt++)
            #pragma unroll
            for (int e = 0; e < 4; e++) acc[mt][nt][e] = 0.f;

    int aoff = (wm * 32 + (lane & 15)) * SAS + (lane >> 4) * 8;
    int boff = (wn * 32 + (lane & 7) + ((lane >> 4) & 1) * 8) * SAS
             + ((lane >> 3) & 1) * 8;

    for (int c = 0; c < NCH; c++) {
        CP_WAIT2();
        __syncthreads();

        int s = c % STG;
        uint32_t st = sbase + (uint32_t)s * STAGE_EL * 2;
        uint32_t sa_h = st, sa_l = st + A_ST * 2;
        uint32_t sb_h = st + 2 * A_ST * 2, sb_l = sb_h + B_ST * 2;

        #pragma unroll
        for (int ks = 0; ks < 2; ks++) {
            uint32_t ah[2][4], al[2][4];
            #pragma unroll
            for (int mt = 0; mt < 2; mt++) {
                uint32_t off = (uint32_t)(aoff + mt * 16 * SAS + ks * 16) * 2;
                ldm_x4(ah[mt], sa_h + off);
                ldm_x4(al[mt], sa_l + off);
            }
            uint32_t bh[2][4], bl[2][4];
            #pragma unroll
            for (int np = 0; np < 2; np++) {
                uint32_t off = (uint32_t)(boff + np * 16 * SAS + ks * 16) * 2;
                ldm_x4(bh[np], sb_h + off);
                ldm_x4(bl[np], sb_l + off);
            }
            #pragma unroll
            for (int mt = 0; mt < 2; mt++)
                #pragma unroll
                for (int nt = 0; nt < 4; nt++) {
                    const uint32_t* Bhf = &bh[nt >> 1][(nt & 1) * 2];
                    const uint32_t* Blf = &bl[nt >> 1][(nt & 1) * 2];
                    mma_bf16(acc[mt][nt], ah[mt], Bhf);
                    mma_bf16(acc[mt][nt], ah[mt], Blf);
                    mma_bf16(acc[mt][nt], al[mt], Bhf);
                }
        }
        __syncthreads();
        if (c + STG < NCH) issue(s, c + STG);
        CP_COMMIT();                        // unconditional: keeps group count
    }

    int mbase = m0 + wm * 32 + (lane >> 2);
    int nbase = n0 + wn * 32 + (lane & 3) * 2;

    if (z == 3) {
        #pragma unroll
        for (int mt = 0; mt < 2; mt++)
            #pragma unroll
            for (int nt = 0; nt < 4; nt++) {
                int mm = mbase + mt * 16, nn = nbase + nt * 8;
                *(float2*)(g_BR + (size_t)mm * DM + nn) =
                    make_float2(acc[mt][nt][0], acc[mt][nt][1]);
                *(float2*)(g_BR + (size_t)(mm + 8) * DM + nn) =
                    make_float2(acc[mt][nt][2], acc[mt][nt][3]);
            }
    } else if (z == 2) {
        #pragma unroll
        for (int mt = 0; mt < 2; mt++)
            #pragma unroll
            for (int nt = 0; nt < 4; nt++) {
                int mm = mbase + mt * 16, nn = nbase + nt * 8;
                #pragma unroll
                for (int half = 0; half < 2; half++) {
                    float x = acc[mt][nt][half * 2], y = acc[mt][nt][half * 2 + 1];
                    float hx = __bfloat162float(__float2bfloat16(x));
                    float hy = __bfloat162float(__float2bfloat16(y));
                    size_t o = (size_t)(mm + half * 8) * DM + nn;
                    *(uint32_t*)(g_Vhi + o) = pack_bf16(x, y);
                    *(uint32_t*)(g_Vlo + o) = pack_bf16(x - hx, y - hy);
                }
            }
    } else {
        __nv_bfloat16* Dhi = (z == 0) ? g_Qhi : g_Khi;
        __nv_bfloat16* Dlo = (z == 0) ? g_Qlo : g_Klo;
        float qscale = (z == 0) ? 0.125f : 1.0f;
        #pragma unroll
        for (int nt = 0; nt < 4; nt++) {
            int nn = nbase + nt * 8;
            int i = (nn & 63) >> 1;   // rope pair index within head
            float inv = (float)exp(-(double)i * (9.210340371976184 / 32.0));
            #pragma unroll
            for (int mt = 0; mt < 2; mt++) {
                #pragma unroll
                for (int half = 0; half < 2; half++) {
                    int mm = mbase + mt * 16 + half * 8;
                    float x1 = acc[mt][nt][half * 2];
                    float x2 = acc[mt][nt][half * 2 + 1];
                    float sa, ca;
                    sincosf((float)mm * inv, &sa, &ca);
                    size_t o = (size_t)mm * DM + nn;
                    float2 br = *(const float2*)(g_BR + o);
                    float e  = (x1 * ca - x2 * sa) * br.x * qscale;
                    float od = (x1 * sa + x2 * ca) * br.y * qscale;
                    float eh = __bfloat162float(__float2bfloat16(e));
                    float oh = __bfloat162float(__float2bfloat16(od));
                    *(uint32_t*)(Dhi + o) = pack_bf16(e, od);
                    *(uint32_t*)(Dlo + o) = pack_bf16(e - eh, od - oh);
                }
            }
        }
    }
}

// ---------------------------------------------------------------------------
// attn_mma: flash attention on mma.sync (unchanged from R9).
// ---------------------------------------------------------------------------
#define VS 72

__global__ __launch_bounds__(512) void attn_mma(
    const unsigned int* __restrict__ mask, float* __restrict__ out)
{
    extern __shared__ __align__(16) char dyn[];
    __nv_bfloat16* sQh = (__nv_bfloat16*)dyn;            // 256 x VS
    __nv_bfloat16* sQl = sQh + 256 * VS;
    __nv_bfloat16* sKh = sQl + 256 * VS;                 // 64 x VS
    __nv_bfloat16* sKl = sKh + 64 * VS;
    __nv_bfloat16* sVh = sKl + 64 * VS;
    __nv_bfloat16* sVl = sVh + 64 * VS;
    unsigned char* smk = (unsigned char*)(sVl + 64 * VS);

    int h = blockIdx.y, m0 = blockIdx.x * 256;
    int tid = threadIdx.x, lane = tid & 31, wid = tid >> 5;

    for (int i = tid; i < SEQ; i += 512)
        smk[i] = (mask[i] != 0u) ? 1 : 0;

    #pragma unroll
    for (int i = 0; i < 8; i++) {
        int f = tid + i * 512, row = f >> 4, c4 = f & 15;
        size_t g = (size_t)(m0 + row) * DM + h * DK + c4 * 4;
        *(uint2*)(sQh + row * VS + c4 * 4) = *(const uint2*)(g_Qhi + g);
        *(uint2*)(sQl + row * VS + c4 * 4) = *(const uint2*)(g_Qlo + g);
    }

    int r0 = m0 + wid * 16 + (lane >> 2);
    bool mr0 = (mask[r0] != 0u), mr1 = (mask[r0 + 8] != 0u);

    float mx0 = -INFINITY, mx1 = -INFINITY, l0 = 0.f, l1 = 0.f;
    float O[8][4];
    #pragma unroll
    for (int nt = 0; nt < 8; nt++)
        #pragma unroll
        for (int e = 0; e < 4; e++) O[nt][e] = 0.f;

    uint32_t sqh = smem_u32(sQh), sql = smem_u32(sQl);
    uint32_t skh = smem_u32(sKh), skl = smem_u32(sKl);
    uint32_t svh = smem_u32(sVh), svl = smem_u32(sVl);

    int qoff = (wid * 16 + (lane & 15)) * VS + (lane >> 4) * 8;
    int kboff = ((lane & 7) + ((lane >> 4) & 1) * 8) * VS + ((lane >> 3) & 1) * 8;
    int voff = (lane & 15) * VS + ((lane >> 4) & 1) * 8;

    int prow[2], pc4[2];
    #pragma unroll
    for (int i = 0; i < 2; i++) { int f = tid + i * 512; prow[i] = f >> 4; pc4[i] = f & 15; }
    uint2 pkh[2], pkl[2], pvh[2], pvl[2];
    #pragma unroll
    for (int i = 0; i < 2; i++) {
        size_t g = (size_t)prow[i] * DM + h * DK + pc4[i] * 4;
        pkh[i] = *(const uint2*)(g_Khi + g);
        pkl[i] = *(const uint2*)(g_Klo + g);
        pvh[i] = *(const uint2*)(g_Vhi + g);
        pvl[i] = *(const uint2*)(g_Vlo + g);
    }

    for (int kb = 0; kb < SEQ / 64; kb++) {
        #pragma unroll
        for (int i = 0; i < 2; i++) {
            int so = prow[i] * VS + pc4[i] * 4;
            *(uint2*)(sKh + so) = pkh[i];
            *(uint2*)(sKl + so) = pkl[i];
            *(uint2*)(sVh + so) = pvh[i];
            *(uint2*)(sVl + so) = pvl[i];
        }
        __syncthreads();

        if (kb + 1 < SEQ / 64) {
            #pragma unroll
            for (int i = 0; i < 2; i++) {
                size_t g = (size_t)((kb + 1) * 64 + prow[i]) * DM + h * DK + pc4[i] * 4;
                pkh[i] = *(const uint2*)(g_Khi + g);
                pkl[i] = *(const uint2*)(g_Klo + g);
                pvh[i] = *(const uint2*)(g_Vhi + g);
                pvl[i] = *(const uint2*)(g_Vlo + g);
            }
        }

        float S[8][4];
        #pragma unroll
        for (int nt = 0; nt < 8; nt++)
            #pragma unroll
            for (int e = 0; e < 4; e++) S[nt][e] = 0.f;

        #pragma unroll
        for (int ks = 0; ks < 4; ks++) {
            uint32_t qh[4], ql[4];
            ldm_x4(qh, sqh + (uint32_t)(qoff + ks * 16) * 2);
            ldm_x4(ql, sql + (uint32_t)(qoff + ks * 16) * 2);
            #pragma unroll
            for (int np = 0; np < 4; np++) {
                uint32_t bh[4], bl[4];
                uint32_t off = (uint32_t)(kboff + np * 16 * VS + ks * 16) * 2;
                ldm_x4(bh, skh + off);
                ldm_x4(bl, skl + off);
                mma_bf16(S[2 * np],     qh, &bh[0]);
                mma_bf16(S[2 * np],     qh, &bl[0]);
                mma_bf16(S[2 * np],     ql, &bh[0]);
                mma_bf16(S[2 * np + 1], qh, &bh[2]);
                mma_bf16(S[2 * np + 1], qh, &bl[2]);
                mma_bf16(S[2 * np + 1], ql, &bh[2]);
            }
        }

        float tm0 = -INFINITY, tm1 = -INFINITY;
        #pragma unroll
        for (int nt = 0; nt < 8; nt++) {
            int col = kb * 64 + nt * 8 + (lane & 3) * 2;
            bool c0 = smk[col] != 0, c1 = smk[col + 1] != 0;
            S[nt][0] = (mr0 && c0) ? S[nt][0] : -1e30f;
            S[nt][1] = (mr0 && c1) ? S[nt][1] : -1e30f;
            S[nt][2] = (mr1 && c0) ? S[nt][2] : -1e30f;
            S[nt][3] = (mr1 && c1) ? S[nt][3] : -1e30f;
            tm0 = fmaxf(tm0, fmaxf(S[nt][0], S[nt][1]));
            tm1 = fmaxf(tm1, fmaxf(S[nt][2], S[nt][3]));
        }
        tm0 = fmaxf(tm0, __shfl_xor_sync(0xffffffffu, tm0, 1));
        tm0 = fmaxf(tm0, __shfl_xor_sync(0xffffffffu, tm0, 2));
        tm1 = fmaxf(tm1, __shfl_xor_sync(0xffffffffu, tm1, 1));
        tm1 = fmaxf(tm1, __shfl_xor_sync(0xffffffffu, tm1, 2));

        if (tm0 > mx0) {
            float sc = __expf(mx0 - tm0);
            l0 *= sc;
            #pragma unroll
            for (int nt = 0; nt < 8; nt++) { O[nt][0] *= sc; O[nt][1] *= sc; }
            mx0 = tm0;
        }
        if (tm1 > mx1) {
            float sc = __expf(mx1 - tm1);
            l1 *= sc;
            #pragma unroll
            for (int nt = 0; nt < 8; nt++) { O[nt][2] *= sc; O[nt][3] *= sc; }
            mx1 = tm1;
        }

        uint32_t P0[8], P1[8];
        #pragma unroll
        for (int nt = 0; nt < 8; nt++) {
            float p0 = __expf(S[nt][0] - mx0);
            float p1 = __expf(S[nt][1] - mx0);
            float p2 = __expf(S[nt][2] - mx1);
            float p3 = __expf(S[nt][3] - mx1);
            uint32_t a = pack_bf16(p0, p1);
            uint32_t b = pack_bf16(p2, p3);
            P0[nt] = a; P1[nt] = b;
            l0 += bf2sum(a);
            l1 += bf2sum(b);
        }

        #pragma unroll
        for (int ks2 = 0; ks2 < 4; ks2++) {
            uint32_t af[4] = {P0[2 * ks2], P1[2 * ks2],
                              P0[2 * ks2 + 1], P1[2 * ks2 + 1]};
            #pragma unroll
            for (int np = 0; np < 4; np++) {
                uint32_t vh[4], vl[4];
                uint32_t off = (uint32_t)(voff + ks2 * 16 * VS + np * 16) * 2;
                ldm_x4t(vh, svh + off);
                ldm_x4t(vl, svl + off);
                mma_bf16(O[2 * np],     af, &vh[0]);
                mma_bf16(O[2 * np],     af, &vl[0]);
                mma_bf16(O[2 * np + 1], af, &vh[2]);
                mma_bf16(O[2 * np + 1], af, &vl[2]);
            }
        }
        __syncthreads();
    }

    l0 += __shfl_xor_sync(0xffffffffu, l0, 1);
    l0 += __shfl_xor_sync(0xffffffffu, l0, 2);
    l1 += __shfl_xor_sync(0xffffffffu, l1, 1);
    l1 += __shfl_xor_sync(0xffffffffu, l1, 2);
    float i0 = 1.f / l0, i1 = 1.f / l1;

    #pragma unroll
    for (int nt = 0; nt < 8; nt++) {
        int nn = h * DK + nt * 8 + (lane & 3) * 2;
        *(float2*)(out + (size_t)r0 * DM + nn) =
            make_float2(O[nt][0] * i0, O[nt][1] * i0);
        *(float2*)(out + (size_t)(r0 + 8) * DM + nn) =
            make_float2(O[nt][2] * i1, O[nt][3] * i1);
    }
}

// ---------------------------------------------------------------------------
extern "C" void kernel_launch(void* const* d_in, const int* in_sizes, int n_in,
                              void* d_out, int out_size)
{
    const float* query = (const float*)d_in[0];
    const float* key   = (const float*)d_in[1];
    const float* value = (const float*)d_in[2];
    const float* bemb  = (const float*)d_in[3];
    const unsigned int* mask = (const unsigned int*)d_in[4];
    const float* LL    = (const float*)d_in[5];
    const float* bproj = (const float*)d_in[6];
    float* out = (float*)d_out;

    static int smem_set = 0;
    if (!smem_set) {
        cudaFuncSetAttribute(attn_mma,
                             cudaFuncAttributeMaxDynamicSharedMemorySize,
                             120 * 1024);
        cudaFuncSetAttribute(proj_mma,
                             cudaFuncAttributeMaxDynamicSharedMemorySize,
                             PROJ_SMEM);
        smem_set = 1;
    }
    const int ATTN_SMEM = (2 * 256 * VS + 4 * 64 * VS) * 2 + SEQ;

    conv_x<<<4 * SEQ * DM / 4 / 256, 256>>>(query, key, value, bemb);
    conv_w<<<dim3(DM / 32, DM / 32, 4), 256>>>(LL, bproj);

    proj_mma<<<dim3(DM / 64, SEQ / 128, 1), 256, PROJ_SMEM>>>(3);  // b_rotate
    proj_mma<<<dim3(DM / 64, SEQ / 128, 3), 256, PROJ_SMEM>>>(0);  // Q,K,V

    attn_mma<<<dim3(SEQ / 256, NH), 512, ATTN_SMEM>>>(mask, out);
}